// round 2
// baseline (speedup 1.0000x reference)
#include <cuda_runtime.h>
#include <math.h>

#define C_DIM   768
#define NCLS    200
#define BATCH   16
#define M_ROWS  (BATCH * 784)   // 12544
#define FF_ELEMS (BATCH * 64 * 768)              // 786432
#define IMG_OUT_ELEMS (BATCH * 3 * 224 * 224)    // 2408448

typedef unsigned long long ull;

// packed fp32x2 FMA (Blackwell FFMA2): d.lo=a.lo*b.lo+c.lo, d.hi=a.hi*b.hi+c.hi
#define FMA_F32X2(d, a, b, c) \
    asm("fma.rn.f32x2 %0, %1, %2, %3;" : "=l"(d) : "l"(a), "l"(b), "l"(c))

__device__ __forceinline__ float ull_lo(ull v) {
    return __uint_as_float((unsigned)(v & 0xffffffffull));
}
__device__ __forceinline__ float ull_hi(ull v) {
    return __uint_as_float((unsigned)(v >> 32));
}

// ---------------- scratch (device globals; no runtime alloc allowed) -------
__device__ float g_maxprob[M_ROWS];
__device__ int   g_sel[BATCH];
__device__ float g_A[3][BATCH * 64 * C_DIM];   // outl / outm / outs, [m][c]

// ===========================================================================
// Kernel 1: logits = x @ W_fc^T + b_fc ; maxprob = 1/sum(exp(l - lmax))
// M=12544, N=200 (padded 224), K=768. BM=64 rows/block, FFMA2 row-pair packed.
// 8 warps; warp w owns rows [8w,8w+8) as 4 row-pairs; lane owns cols lane+32j.
// ===========================================================================
#define XST 72     // xs_t stride (floats)
#define WST 456    // ws stride (floats) = 224 duplicated pairs + pad

__global__ __launch_bounds__(256, 2)
void fc_softmax_kernel(const float* __restrict__ x,
                       const float* __restrict__ Wfc,
                       const float* __restrict__ bfc)
{
    __shared__ float xs_t[16 * XST];   // [k][row]
    __shared__ float ws[16 * WST];     // [k][2n] = [k][2n+1] = W[n][k]

    const int tid  = threadIdx.x;
    const int lane = tid & 31;
    const int warp = tid >> 5;
    const int m0   = blockIdx.x * 64;

    // fill mappings
    const int xrow = tid >> 2, xkq = tid & 3;                 // x: 1 float4/thread
    const float* xptr = x + (size_t)(m0 + xrow) * C_DIM + xkq * 4;

    ull acc[4][7];
#pragma unroll
    for (int i = 0; i < 4; i++)
#pragma unroll
        for (int j = 0; j < 7; j++) acc[i][j] = 0ull;

    // prefetch tile 0 into registers
    float4 xreg = *(const float4*)xptr;
    float  wreg[14];
#pragma unroll
    for (int it = 0; it < 14; it++) {
        int idx = tid + it * 256;
        int k = idx & 15, n = idx >> 4;
        wreg[it] = (n < NCLS) ? Wfc[(size_t)n * C_DIM + k] : 0.f;
    }

    for (int t = 0; t < 48; t++) {
        __syncthreads();
        xs_t[(xkq * 4 + 0) * XST + xrow] = xreg.x;
        xs_t[(xkq * 4 + 1) * XST + xrow] = xreg.y;
        xs_t[(xkq * 4 + 2) * XST + xrow] = xreg.z;
        xs_t[(xkq * 4 + 3) * XST + xrow] = xreg.w;
#pragma unroll
        for (int it = 0; it < 14; it++) {
            int idx = tid + it * 256;
            int k = idx & 15, n = idx >> 4;
            *(float2*)&ws[k * WST + 2 * n] = make_float2(wreg[it], wreg[it]);
        }
        __syncthreads();

        if (t < 47) {
            int k0 = (t + 1) * 16;
            xreg = *(const float4*)(xptr + k0);
#pragma unroll
            for (int it = 0; it < 14; it++) {
                int idx = tid + it * 256;
                int k = idx & 15, n = idx >> 4;
                wreg[it] = (n < NCLS) ? Wfc[(size_t)n * C_DIM + k0 + k] : 0.f;
            }
        }

#pragma unroll
        for (int kk = 0; kk < 16; kk++) {
            ull xp[4], wp[7];
#pragma unroll
            for (int i = 0; i < 4; i++)
                xp[i] = *(const ull*)&xs_t[kk * XST + warp * 8 + 2 * i];
#pragma unroll
            for (int j = 0; j < 7; j++)
                wp[j] = *(const ull*)&ws[kk * WST + (lane + 32 * j) * 2];
#pragma unroll
            for (int i = 0; i < 4; i++)
#pragma unroll
                for (int j = 0; j < 7; j++)
                    FMA_F32X2(acc[i][j], xp[i], wp[j], acc[i][j]);
        }
    }

    // bias + per-row max / sum(exp) via warp shuffles
    float bn[7];
#pragma unroll
    for (int j = 0; j < 7; j++) {
        int n = lane + 32 * j;
        bn[j] = (n < NCLS) ? bfc[n] : 0.f;
    }
#pragma unroll
    for (int rp = 0; rp < 4; rp++) {
#pragma unroll
        for (int half = 0; half < 2; half++) {
            float l[7];
#pragma unroll
            for (int j = 0; j < 7; j++)
                l[j] = (half ? ull_hi(acc[rp][j]) : ull_lo(acc[rp][j])) + bn[j];
            float mx = -1e30f;
#pragma unroll
            for (int j = 0; j < 7; j++) {
                int n = lane + 32 * j;
                if (n < NCLS) mx = fmaxf(mx, l[j]);
            }
#pragma unroll
            for (int off = 16; off > 0; off >>= 1)
                mx = fmaxf(mx, __shfl_xor_sync(0xffffffffu, mx, off));
            float s = 0.f;
#pragma unroll
            for (int j = 0; j < 7; j++) {
                int n = lane + 32 * j;
                if (n < NCLS) s += expf(l[j] - mx);
            }
#pragma unroll
            for (int off = 16; off > 0; off >>= 1)
                s += __shfl_xor_sync(0xffffffffu, s, off);
            if (lane == 0) g_maxprob[m0 + warp * 8 + 2 * rp + half] = 1.f / s;
        }
    }
}

// ===========================================================================
// Kernel 2: part_logits (8x8 mean-pool, stride 3, pad 2) * mask -> argmax
// ===========================================================================
__global__ void sel_kernel(const float* __restrict__ mask)
{
    int b = blockIdx.x;
    __shared__ float vals[81];
    int p = threadIdx.x;
    if (p < 81) {
        int oy = p / 9, ox = p % 9;
        float s = 0.f;
        for (int i = 0; i < 8; i++) {
            int h = oy * 3 - 2 + i;
            if (h < 0 || h >= 28) continue;
            for (int j = 0; j < 8; j++) {
                int w = ox * 3 - 2 + j;
                if (w < 0 || w >= 28) continue;
                s += g_maxprob[b * 784 + h * 28 + w];
            }
        }
        vals[p] = mask[b * 81 + p] * (s * (1.f / 64.f));
    }
    __syncthreads();
    if (p == 0) {
        float best = vals[0];
        int bi = 0;
        for (int q = 1; q < 81; q++)
            if (vals[q] > best) { best = vals[q]; bi = q; }
        g_sel[b] = bi;
    }
}

// ===========================================================================
// Kernel 3: gather selected patches (+ clamped half-pixel bilinear for 6x6/4x4)
// ===========================================================================
__global__ void gather_kernel(const float* __restrict__ x)
{
    int p    = blockIdx.x;
    int b    = blockIdx.y;
    int part = blockIdx.z;
    int sel  = g_sel[b];
    int oy = sel / 9, ox = sel % 9;
    int i = p >> 3, j = p & 7;

    const float* xb = x + (size_t)b * 784 * C_DIM;
    float* out = &g_A[part][(size_t)(b * 64 + p) * C_DIM];

    if (part == 0) {
        int h = oy * 3 - 2 + i, w = ox * 3 - 2 + j;
        bool ok = (h >= 0 && h < 28 && w >= 0 && w < 28);
        const float* src = xb + (size_t)(ok ? (h * 28 + w) : 0) * C_DIM;
        for (int c = threadIdx.x; c < C_DIM; c += blockDim.x)
            out[c] = ok ? src[c] : 0.f;
    } else {
        int   n, basepad;
        float scale, offs;
        if (part == 1) { n = 6; basepad = 1; scale = 0.75f; offs = -0.125f; }
        else           { n = 4; basepad = 0; scale = 0.5f;  offs = -0.25f;  }
        float sy = fminf(fmaxf(scale * i + offs, 0.f), (float)(n - 1));
        float sx = fminf(fmaxf(scale * j + offs, 0.f), (float)(n - 1));
        int iy0 = (int)sy; float fy = sy - iy0; int iy1 = min(iy0 + 1, n - 1);
        int ix0 = (int)sx; float fx = sx - ix0; int ix1 = min(ix0 + 1, n - 1);
        int hb = oy * 3 - basepad, wb = ox * 3 - basepad;
        int h0 = hb + iy0, h1 = hb + iy1, w0 = wb + ix0, w1 = wb + ix1;
        bool okh0 = (h0 >= 0 && h0 < 28), okh1 = (h1 >= 0 && h1 < 28);
        bool okw0 = (w0 >= 0 && w0 < 28), okw1 = (w1 >= 0 && w1 < 28);
        bool ok00 = okh0 && okw0, ok01 = okh0 && okw1;
        bool ok10 = okh1 && okw0, ok11 = okh1 && okw1;
        size_t o00 = (size_t)(ok00 ? (h0 * 28 + w0) : 0) * C_DIM;
        size_t o01 = (size_t)(ok01 ? (h0 * 28 + w1) : 0) * C_DIM;
        size_t o10 = (size_t)(ok10 ? (h1 * 28 + w0) : 0) * C_DIM;
        size_t o11 = (size_t)(ok11 ? (h1 * 28 + w1) : 0) * C_DIM;
        for (int c = threadIdx.x; c < C_DIM; c += blockDim.x) {
            float v00 = ok00 ? xb[o00 + c] : 0.f;
            float v01 = ok01 ? xb[o01 + c] : 0.f;
            float v10 = ok10 ? xb[o10 + c] : 0.f;
            float v11 = ok11 ? xb[o11 + c] : 0.f;
            out[c] = (1.f - fy) * ((1.f - fx) * v00 + fx * v01)
                   +        fy  * ((1.f - fx) * v10 + fx * v11);
        }
    }
}

// ===========================================================================
// Kernel 4: parts GEMM.  C[1024, 768] = [A0@Wl^T | A1@Wm^T | A2@Ws^T] + bias.
// BM=64, BN=64, BK=32; FFMA2 row-pair packed; register-prefetch pipeline.
// ===========================================================================
#define AST  72   // as_t stride (floats)
#define BST2 66   // bsd stride (float2)

__global__ __launch_bounds__(256, 2)
void parts_gemm_kernel(const float* __restrict__ Wl, const float* __restrict__ bl,
                       const float* __restrict__ Wm, const float* __restrict__ bm,
                       const float* __restrict__ Ws, const float* __restrict__ bsv,
                       float* __restrict__ out)
{
    const int ny = blockIdx.y;
    int part, noff;
    const float *W, *bias;
    if (ny < 3)      { part = 0; W = Wl; bias = bl;  noff = 0;   }
    else if (ny < 6) { part = 1; W = Wm; bias = bm;  noff = 192; }
    else             { part = 2; W = Ws; bias = bsv; noff = 384; }
    const int n0_cat  = ny * 64;
    const int n0_part = n0_cat - noff;
    const float* A = g_A[part];
    const int m0 = blockIdx.x * 64;

    __shared__ float  as_t[32 * AST];     // [k][row]
    __shared__ float2 bsd[32 * BST2];     // [k][col] = (w,w)

    const int tid   = threadIdx.x;
    const int row_t = tid >> 4;       // 0..15 -> rows row_t*4..+3
    const int col_t = tid & 15;       // 0..15 -> cols col_t*4..+3

    // fill mapping: fidx = tid + 256*it (it<2): r/c = fidx>>3, kq = fidx&7
    const int frow = tid >> 3;        // it=0 -> rows/cols 0..31, it=1 -> 32..63
    const int fkq  = tid & 7;

    ull acc[2][4];
#pragma unroll
    for (int p = 0; p < 2; p++)
#pragma unroll
        for (int c = 0; c < 4; c++) acc[p][c] = 0ull;

    float4 areg[2], breg[2];
#pragma unroll
    for (int it = 0; it < 2; it++) {
        int r = frow + it * 32;
        areg[it] = *(const float4*)&A[(size_t)(m0 + r) * C_DIM + fkq * 4];
        breg[it] = *(const float4*)&W[(size_t)(n0_part + r) * C_DIM + fkq * 4];
    }

    for (int t = 0; t < 24; t++) {
        __syncthreads();
#pragma unroll
        for (int it = 0; it < 2; it++) {
            int r = frow + it * 32;
            as_t[(fkq * 4 + 0) * AST + r] = areg[it].x;
            as_t[(fkq * 4 + 1) * AST + r] = areg[it].y;
            as_t[(fkq * 4 + 2) * AST + r] = areg[it].z;
            as_t[(fkq * 4 + 3) * AST + r] = areg[it].w;
            bsd[(fkq * 4 + 0) * BST2 + r] = make_float2(breg[it].x, breg[it].x);
            bsd[(fkq * 4 + 1) * BST2 + r] = make_float2(breg[it].y, breg[it].y);
            bsd[(fkq * 4 + 2) * BST2 + r] = make_float2(breg[it].z, breg[it].z);
            bsd[(fkq * 4 + 3) * BST2 + r] = make_float2(breg[it].w, breg[it].w);
        }
        __syncthreads();

        if (t < 23) {
            int k0 = (t + 1) * 32;
#pragma unroll
            for (int it = 0; it < 2; it++) {
                int r = frow + it * 32;
                areg[it] = *(const float4*)&A[(size_t)(m0 + r) * C_DIM + k0 + fkq * 4];
                breg[it] = *(const float4*)&W[(size_t)(n0_part + r) * C_DIM + k0 + fkq * 4];
            }
        }

#pragma unroll
        for (int kk = 0; kk < 32; kk++) {
            ull a0 = *(const ull*)&as_t[kk * AST + row_t * 4];
            ull a1 = *(const ull*)&as_t[kk * AST + row_t * 4 + 2];
            ull bp[4];
#pragma unroll
            for (int c = 0; c < 4; c++)
                bp[c] = *(const ull*)&bsd[kk * BST2 + col_t * 4 + c];
#pragma unroll
            for (int c = 0; c < 4; c++) {
                FMA_F32X2(acc[0][c], a0, bp[c], acc[0][c]);
                FMA_F32X2(acc[1][c], a1, bp[c], acc[1][c]);
            }
        }
    }

#pragma unroll
    for (int c = 0; c < 4; c++) {
        int npart = n0_part + col_t * 4 + c;
        float bval = bias[npart];
#pragma unroll
        for (int p = 0; p < 2; p++) {
            int m_lo = m0 + row_t * 4 + 2 * p;
            out[(size_t)m_lo * 768 + n0_cat + col_t * 4 + c]       = ull_lo(acc[p][c]) + bval;
            out[(size_t)(m_lo + 1) * 768 + n0_cat + col_t * 4 + c] = ull_hi(acc[p][c]) + bval;
        }
    }
}

// ===========================================================================
// Kernel 5: image patch gather (128x128 @ stride 48, pad 32) + bilinear 224.
// ===========================================================================
__global__ void image_kernel(const float* __restrict__ img, float* __restrict__ out)
{
    int idx = blockIdx.x * blockDim.x + threadIdx.x;
    if (idx >= IMG_OUT_ELEMS) return;
    int ox = idx % 224;
    int oy = (idx / 224) % 224;
    int ch = (idx / (224 * 224)) % 3;
    int b  = idx / (3 * 224 * 224);

    int sel = g_sel[b];
    int r0 = (sel / 9) * 48 - 32;
    int c0 = (sel % 9) * 48 - 32;

    const float s = 128.f / 224.f;
    float sy = fminf(fmaxf((oy + 0.5f) * s - 0.5f, 0.f), 127.f);
    float sx = fminf(fmaxf((ox + 0.5f) * s - 0.5f, 0.f), 127.f);
    int py0 = (int)sy; float fy = sy - py0; int py1 = min(py0 + 1, 127);
    int px0 = (int)sx; float fx = sx - px0; int px1 = min(px0 + 1, 127);

    const float* ib = img + (size_t)(b * 3 + ch) * 448 * 448;
    int gy0 = r0 + py0, gy1 = r0 + py1, gx0 = c0 + px0, gx1 = c0 + px1;
    bool oky0 = (gy0 >= 0 && gy0 < 448), oky1 = (gy1 >= 0 && gy1 < 448);
    bool okx0 = (gx0 >= 0 && gx0 < 448), okx1 = (gx1 >= 0 && gx1 < 448);
    float v00 = (oky0 && okx0) ? ib[gy0 * 448 + gx0] : 0.f;
    float v01 = (oky0 && okx1) ? ib[gy0 * 448 + gx1] : 0.f;
    float v10 = (oky1 && okx0) ? ib[gy1 * 448 + gx0] : 0.f;
    float v11 = (oky1 && okx1) ? ib[gy1 * 448 + gx1] : 0.f;

    out[idx] = (1.f - fy) * ((1.f - fx) * v00 + fx * v01)
             +        fy  * ((1.f - fx) * v10 + fx * v11);
}

// ===========================================================================
extern "C" void kernel_launch(void* const* d_in, const int* in_sizes, int n_in,
                              void* d_out, int out_size)
{
    const float* x    = (const float*)d_in[0];
    const float* mask = (const float*)d_in[1];
    const float* img  = (const float*)d_in[2];
    const float* Wfc  = (const float*)d_in[3];
    const float* bfc  = (const float*)d_in[4];
    const float* Wl   = (const float*)d_in[5];
    const float* bl   = (const float*)d_in[6];
    const float* Wm   = (const float*)d_in[7];
    const float* bm   = (const float*)d_in[8];
    const float* Ws   = (const float*)d_in[9];
    const float* bsv  = (const float*)d_in[10];

    float* out_ff  = (float*)d_out;                 // [16,64,768]
    float* out_img = (float*)d_out + FF_ELEMS;      // [16,3,224,224]

    fc_softmax_kernel<<<M_ROWS / 64, 256>>>(x, Wfc, bfc);
    sel_kernel<<<BATCH, 128>>>(mask);
    {
        dim3 g(64, BATCH, 3);
        gather_kernel<<<g, 256>>>(x);
    }
    {
        dim3 g(16, 12);
        parts_gemm_kernel<<<g, 256>>>(Wl, bl, Wm, bm, Ws, bsv, out_ff);
    }
    image_kernel<<<(IMG_OUT_ELEMS + 255) / 256, 256>>>(img, out_img);
}

// round 3
// speedup vs baseline: 1.6731x; 1.6731x over previous
#include <cuda_runtime.h>
#include <math.h>

#define C_DIM   768
#define NCLS    200
#define BATCH   16
#define M_ROWS  (BATCH * 784)   // 12544
#define FF_ELEMS (BATCH * 64 * 768)              // 786432
#define IMG_OUT_ELEMS (BATCH * 3 * 224 * 224)    // 2408448

// ---------------- scratch (device globals; no runtime alloc allowed) -------
__device__ float g_maxprob[M_ROWS];
__device__ int   g_sel[BATCH];
__device__ float g_A[3][BATCH * 64 * C_DIM];   // outl / outm / outs, [m][c]

// ===========================================================================
// Kernel 1: logits = x @ W_fc^T + b_fc ; maxprob = 1/sum(exp(l - lmax))
// M=12544, N=200 (padded 224), K=768. BM=32 rows/CTA (small quantum => 392
// CTAs => per-SM load balance). 128 threads = 4 warps; warp w owns rows
// [8w,8w+8); lane owns cols lane+32j, j<7. Register-prefetch pipeline.
// ===========================================================================
#define WST 225   // ws row stride (odd -> conflict-free)

__global__ __launch_bounds__(128, 4)
void fc_softmax_kernel(const float* __restrict__ x,
                       const float* __restrict__ Wfc,
                       const float* __restrict__ bfc)
{
    __shared__ float xs[32][17];
    __shared__ float ws[16 * WST];   // [k][n], n<224, rows 200..223 zero

    const int tid  = threadIdx.x;
    const int lane = tid & 31;
    const int warp = tid >> 5;
    const int m0   = blockIdx.x * 32;

    // zero-pad ws columns 200..223 once (never overwritten in the loop)
#pragma unroll
    for (int it = 0; it < 3; it++) {
        int idx = tid + it * 128;          // 0..383
        int n = 200 + (idx % 24);
        int k = idx / 24;                  // 0..15
        ws[k * WST + n] = 0.f;
    }

    // fill mappings
    const int xrow = tid >> 2, xkq = tid & 3;      // X: 1 float4/thread
    const float* xptr = x + (size_t)(m0 + xrow) * C_DIM + xkq * 4;

    float acc[8][7];
#pragma unroll
    for (int r = 0; r < 8; r++)
#pragma unroll
        for (int j = 0; j < 7; j++) acc[r][j] = 0.f;

    // prefetch tile 0
    float4 xreg = *(const float4*)xptr;
    float4 wreg[7];
#pragma unroll
    for (int it = 0; it < 7; it++) {
        int c = tid + it * 128;            // 0..895, valid < 800
        if (c < 800) {
            int n = c >> 2, kq = c & 3;
            wreg[it] = *(const float4*)&Wfc[(size_t)n * C_DIM + kq * 4];
        }
    }

    for (int t = 0; t < 48; t++) {
        __syncthreads();   // previous compute done; safe to overwrite tiles
        xs[xrow][xkq * 4 + 0] = xreg.x;
        xs[xrow][xkq * 4 + 1] = xreg.y;
        xs[xrow][xkq * 4 + 2] = xreg.z;
        xs[xrow][xkq * 4 + 3] = xreg.w;
#pragma unroll
        for (int it = 0; it < 7; it++) {
            int c = tid + it * 128;
            if (c < 800) {
                int n = c >> 2, kq = c & 3;
                ws[(kq * 4 + 0) * WST + n] = wreg[it].x;
                ws[(kq * 4 + 1) * WST + n] = wreg[it].y;
                ws[(kq * 4 + 2) * WST + n] = wreg[it].z;
                ws[(kq * 4 + 3) * WST + n] = wreg[it].w;
            }
        }
        __syncthreads();

        if (t < 47) {
            int k0 = (t + 1) * 16;
            xreg = *(const float4*)(xptr + k0);
#pragma unroll
            for (int it = 0; it < 7; it++) {
                int c = tid + it * 128;
                if (c < 800) {
                    int n = c >> 2, kq = c & 3;
                    wreg[it] = *(const float4*)&Wfc[(size_t)n * C_DIM + k0 + kq * 4];
                }
            }
        }

#pragma unroll
        for (int kk = 0; kk < 16; kk++) {
            float xr[8], wv[7];
#pragma unroll
            for (int r = 0; r < 8; r++) xr[r] = xs[warp * 8 + r][kk];   // bcast
#pragma unroll
            for (int j = 0; j < 7; j++) wv[j] = ws[kk * WST + lane + 32 * j];
#pragma unroll
            for (int r = 0; r < 8; r++)
#pragma unroll
                for (int j = 0; j < 7; j++)
                    acc[r][j] = fmaf(xr[r], wv[j], acc[r][j]);
        }
    }

    // bias + per-row max / sum(exp) via warp shuffles
    float bn[7];
#pragma unroll
    for (int j = 0; j < 7; j++) {
        int n = lane + 32 * j;
        bn[j] = (n < NCLS) ? bfc[n] : 0.f;
    }
#pragma unroll
    for (int r = 0; r < 8; r++) {
        float mx = -1e30f;
#pragma unroll
        for (int j = 0; j < 7; j++) {
            int n = lane + 32 * j;
            float l = acc[r][j] + bn[j];
            if (n < NCLS) mx = fmaxf(mx, l);
        }
#pragma unroll
        for (int off = 16; off > 0; off >>= 1)
            mx = fmaxf(mx, __shfl_xor_sync(0xffffffffu, mx, off));
        float s = 0.f;
#pragma unroll
        for (int j = 0; j < 7; j++) {
            int n = lane + 32 * j;
            float l = acc[r][j] + bn[j];
            if (n < NCLS) s += expf(l - mx);
        }
#pragma unroll
        for (int off = 16; off > 0; off >>= 1)
            s += __shfl_xor_sync(0xffffffffu, s, off);
        if (lane == 0) g_maxprob[m0 + warp * 8 + r] = 1.f / s;
    }
}

// ===========================================================================
// Kernel 2: part_logits (8x8 mean-pool, stride 3, pad 2) * mask -> argmax
// ===========================================================================
__global__ void sel_kernel(const float* __restrict__ mask)
{
    int b = blockIdx.x;
    __shared__ float vals[81];
    int p = threadIdx.x;
    if (p < 81) {
        int oy = p / 9, ox = p % 9;
        float s = 0.f;
        for (int i = 0; i < 8; i++) {
            int h = oy * 3 - 2 + i;
            if (h < 0 || h >= 28) continue;
            for (int j = 0; j < 8; j++) {
                int w = ox * 3 - 2 + j;
                if (w < 0 || w >= 28) continue;
                s += g_maxprob[b * 784 + h * 28 + w];
            }
        }
        vals[p] = mask[b * 81 + p] * (s * (1.f / 64.f));
    }
    __syncthreads();
    if (p == 0) {
        float best = vals[0];
        int bi = 0;
        for (int q = 1; q < 81; q++)
            if (vals[q] > best) { best = vals[q]; bi = q; }
        g_sel[b] = bi;
    }
}

// ===========================================================================
// Kernel 3: gather selected patches (+ clamped half-pixel bilinear 6x6/4x4)
// ===========================================================================
__global__ void gather_kernel(const float* __restrict__ x)
{
    int p    = blockIdx.x;
    int b    = blockIdx.y;
    int part = blockIdx.z;
    int sel  = g_sel[b];
    int oy = sel / 9, ox = sel % 9;
    int i = p >> 3, j = p & 7;

    const float* xb = x + (size_t)b * 784 * C_DIM;
    float* out = &g_A[part][(size_t)(b * 64 + p) * C_DIM];

    if (part == 0) {
        int h = oy * 3 - 2 + i, w = ox * 3 - 2 + j;
        bool ok = (h >= 0 && h < 28 && w >= 0 && w < 28);
        const float* src = xb + (size_t)(ok ? (h * 28 + w) : 0) * C_DIM;
        for (int c = threadIdx.x; c < C_DIM; c += blockDim.x)
            out[c] = ok ? src[c] : 0.f;
    } else {
        int   n, basepad;
        float scale, offs;
        if (part == 1) { n = 6; basepad = 1; scale = 0.75f; offs = -0.125f; }
        else           { n = 4; basepad = 0; scale = 0.5f;  offs = -0.25f;  }
        float sy = fminf(fmaxf(scale * i + offs, 0.f), (float)(n - 1));
        float sx = fminf(fmaxf(scale * j + offs, 0.f), (float)(n - 1));
        int iy0 = (int)sy; float fy = sy - iy0; int iy1 = min(iy0 + 1, n - 1);
        int ix0 = (int)sx; float fx = sx - ix0; int ix1 = min(ix0 + 1, n - 1);
        int hb = oy * 3 - basepad, wb = ox * 3 - basepad;
        int h0 = hb + iy0, h1 = hb + iy1, w0 = wb + ix0, w1 = wb + ix1;
        bool okh0 = (h0 >= 0 && h0 < 28), okh1 = (h1 >= 0 && h1 < 28);
        bool okw0 = (w0 >= 0 && w0 < 28), okw1 = (w1 >= 0 && w1 < 28);
        bool ok00 = okh0 && okw0, ok01 = okh0 && okw1;
        bool ok10 = okh1 && okw0, ok11 = okh1 && okw1;
        size_t o00 = (size_t)(ok00 ? (h0 * 28 + w0) : 0) * C_DIM;
        size_t o01 = (size_t)(ok01 ? (h0 * 28 + w1) : 0) * C_DIM;
        size_t o10 = (size_t)(ok10 ? (h1 * 28 + w0) : 0) * C_DIM;
        size_t o11 = (size_t)(ok11 ? (h1 * 28 + w1) : 0) * C_DIM;
        for (int c = threadIdx.x; c < C_DIM; c += blockDim.x) {
            float v00 = ok00 ? xb[o00 + c] : 0.f;
            float v01 = ok01 ? xb[o01 + c] : 0.f;
            float v10 = ok10 ? xb[o10 + c] : 0.f;
            float v11 = ok11 ? xb[o11 + c] : 0.f;
            out[c] = (1.f - fy) * ((1.f - fx) * v00 + fx * v01)
                   +        fy  * ((1.f - fx) * v10 + fx * v11);
        }
    }
}

// ===========================================================================
// Kernel 4: parts GEMM.  C[1024,768] = [A0@Wl^T | A1@Wm^T | A2@Ws^T] + bias.
// BM=32, BN=64, BK=16; 128 threads, 4x4/thread; grid (32,12)=384 CTAs.
// Register-prefetch pipeline; conflict-free scalar-FFMA layouts.
// ===========================================================================
__global__ __launch_bounds__(128, 6)
void parts_gemm_kernel(const float* __restrict__ Wl, const float* __restrict__ bl,
                       const float* __restrict__ Wm, const float* __restrict__ bm,
                       const float* __restrict__ Ws, const float* __restrict__ bsv,
                       float* __restrict__ out)
{
    const int ny = blockIdx.y;
    int part, noff;
    const float *W, *bias;
    if (ny < 3)      { part = 0; W = Wl; bias = bl;  noff = 0;   }
    else if (ny < 6) { part = 1; W = Wm; bias = bm;  noff = 192; }
    else             { part = 2; W = Ws; bias = bsv; noff = 384; }
    const int n0_cat  = ny * 64;
    const int n0_part = n0_cat - noff;
    const float* A = g_A[part];
    const int m0 = blockIdx.x * 32;

    __shared__ float as[32 * 17];
    __shared__ float bsm[16 * 68];

    const int tid   = threadIdx.x;
    const int row_t = tid >> 4;    // 0..7  -> rows row_t*4..+3
    const int col_t = tid & 15;    // 0..15 -> cols col_t*4..+3

    // fill mappings
    const int arow = tid >> 2, akq = tid & 3;          // A: 1 float4/thread
    const float* aptr = A + (size_t)(m0 + arow) * C_DIM + akq * 4;
    const int brow = tid >> 2, bkq = tid & 3;          // W: 2 float4/thread

    float acc[4][4];
#pragma unroll
    for (int r = 0; r < 4; r++)
#pragma unroll
        for (int c = 0; c < 4; c++) acc[r][c] = 0.f;

    float4 areg = *(const float4*)aptr;
    float4 breg[2];
#pragma unroll
    for (int it = 0; it < 2; it++)
        breg[it] = *(const float4*)&W[(size_t)(n0_part + brow + it * 32) * C_DIM + bkq * 4];

    for (int t = 0; t < 48; t++) {
        __syncthreads();
        as[arow * 17 + akq * 4 + 0] = areg.x;
        as[arow * 17 + akq * 4 + 1] = areg.y;
        as[arow * 17 + akq * 4 + 2] = areg.z;
        as[arow * 17 + akq * 4 + 3] = areg.w;
#pragma unroll
        for (int it = 0; it < 2; it++) {
            int n = brow + it * 32;
            bsm[(bkq * 4 + 0) * 68 + n] = breg[it].x;
            bsm[(bkq * 4 + 1) * 68 + n] = breg[it].y;
            bsm[(bkq * 4 + 2) * 68 + n] = breg[it].z;
            bsm[(bkq * 4 + 3) * 68 + n] = breg[it].w;
        }
        __syncthreads();

        if (t < 47) {
            int k0 = (t + 1) * 16;
            areg = *(const float4*)(aptr + k0);
#pragma unroll
            for (int it = 0; it < 2; it++)
                breg[it] = *(const float4*)&W[(size_t)(n0_part + brow + it * 32) * C_DIM + k0 + bkq * 4];
        }

#pragma unroll
        for (int kk = 0; kk < 16; kk++) {
            float a[4];
#pragma unroll
            for (int r = 0; r < 4; r++) a[r] = as[(row_t * 4 + r) * 17 + kk];
            float4 bv = *(const float4*)&bsm[kk * 68 + col_t * 4];
            float bb[4] = { bv.x, bv.y, bv.z, bv.w };
#pragma unroll
            for (int r = 0; r < 4; r++)
#pragma unroll
                for (int c = 0; c < 4; c++)
                    acc[r][c] = fmaf(a[r], bb[c], acc[r][c]);
        }
    }

#pragma unroll
    for (int c = 0; c < 4; c++) {
        int npart = n0_part + col_t * 4 + c;
        float bval = bias[npart];
#pragma unroll
        for (int r = 0; r < 4; r++) {
            int m = m0 + row_t * 4 + r;
            out[(size_t)m * 768 + n0_cat + col_t * 4 + c] = acc[r][c] + bval;
        }
    }
}

// ===========================================================================
// Kernel 5: image patch gather (128x128 @ stride 48, pad 32) + bilinear 224.
// ===========================================================================
__global__ void image_kernel(const float* __restrict__ img, float* __restrict__ out)
{
    int idx = blockIdx.x * blockDim.x + threadIdx.x;
    if (idx >= IMG_OUT_ELEMS) return;
    int ox = idx % 224;
    int oy = (idx / 224) % 224;
    int ch = (idx / (224 * 224)) % 3;
    int b  = idx / (3 * 224 * 224);

    int sel = g_sel[b];
    int r0 = (sel / 9) * 48 - 32;
    int c0 = (sel % 9) * 48 - 32;

    const float s = 128.f / 224.f;
    float sy = fminf(fmaxf((oy + 0.5f) * s - 0.5f, 0.f), 127.f);
    float sx = fminf(fmaxf((ox + 0.5f) * s - 0.5f, 0.f), 127.f);
    int py0 = (int)sy; float fy = sy - py0; int py1 = min(py0 + 1, 127);
    int px0 = (int)sx; float fx = sx - px0; int px1 = min(px0 + 1, 127);

    const float* ib = img + (size_t)(b * 3 + ch) * 448 * 448;
    int gy0 = r0 + py0, gy1 = r0 + py1, gx0 = c0 + px0, gx1 = c0 + px1;
    bool oky0 = (gy0 >= 0 && gy0 < 448), oky1 = (gy1 >= 0 && gy1 < 448);
    bool okx0 = (gx0 >= 0 && gx0 < 448), okx1 = (gx1 >= 0 && gx1 < 448);
    float v00 = (oky0 && okx0) ? ib[gy0 * 448 + gx0] : 0.f;
    float v01 = (oky0 && okx1) ? ib[gy0 * 448 + gx1] : 0.f;
    float v10 = (oky1 && okx0) ? ib[gy1 * 448 + gx0] : 0.f;
    float v11 = (oky1 && okx1) ? ib[gy1 * 448 + gx1] : 0.f;

    out[idx] = (1.f - fy) * ((1.f - fx) * v00 + fx * v01)
             +        fy  * ((1.f - fx) * v10 + fx * v11);
}

// ===========================================================================
extern "C" void kernel_launch(void* const* d_in, const int* in_sizes, int n_in,
                              void* d_out, int out_size)
{
    const float* x    = (const float*)d_in[0];
    const float* mask = (const float*)d_in[1];
    const float* img  = (const float*)d_in[2];
    const float* Wfc  = (const float*)d_in[3];
    const float* bfc  = (const float*)d_in[4];
    const float* Wl   = (const float*)d_in[5];
    const float* bl   = (const float*)d_in[6];
    const float* Wm   = (const float*)d_in[7];
    const float* bm   = (const float*)d_in[8];
    const float* Ws   = (const float*)d_in[9];
    const float* bsv  = (const float*)d_in[10];

    float* out_ff  = (float*)d_out;                 // [16,64,768]
    float* out_img = (float*)d_out + FF_ELEMS;      // [16,3,224,224]

    fc_softmax_kernel<<<M_ROWS / 32, 128>>>(x, Wfc, bfc);
    sel_kernel<<<BATCH, 128>>>(mask);
    {
        dim3 g(64, BATCH, 3);
        gather_kernel<<<g, 256>>>(x);
    }
    {
        dim3 g(32, 12);
        parts_gemm_kernel<<<g, 128>>>(Wl, bl, Wm, bm, Ws, bsv, out_ff);
    }
    image_kernel<<<(IMG_OUT_ELEMS + 255) / 256, 256>>>(img, out_img);
}

// round 4
// speedup vs baseline: 2.6319x; 1.5730x over previous
#include <cuda_runtime.h>
#include <cuda_bf16.h>
#include <math.h>

typedef unsigned int uint;

#define C_DIM   768
#define NCLS    200
#define BATCH   16
#define M_ROWS  (BATCH * 784)   // 12544
#define NPAD    224
#define FF_ELEMS (BATCH * 64 * 768)              // 786432
#define IMG_OUT_ELEMS (BATCH * 3 * 224 * 224)    // 2408448

// ---------------- scratch (device globals; no runtime alloc allowed) -------
__device__ float g_maxprob[M_ROWS];
__device__ int   g_sel[BATCH];
__device__ __align__(16) float g_logits[(size_t)M_ROWS * NPAD];
__device__ __align__(16) __nv_bfloat16 g_Wfch[NPAD * C_DIM];
__device__ __align__(16) __nv_bfloat16 g_Wfcl[NPAD * C_DIM];
__device__ __align__(16) __nv_bfloat16 g_Wph[768 * C_DIM];
__device__ __align__(16) __nv_bfloat16 g_Wpl[768 * C_DIM];
__device__ __align__(16) float g_bias[768];
__device__ __align__(16) __nv_bfloat16 g_Ah[3][1024 * C_DIM];
__device__ __align__(16) __nv_bfloat16 g_Al[3][1024 * C_DIM];

__device__ __forceinline__ uint b2u(__nv_bfloat162 v) {
    return *reinterpret_cast<uint*>(&v);
}

// bf16 hi/lo split: v = hi + lo + O(2^-17 v)
__device__ __forceinline__ void bf16_split(float a, __nv_bfloat16& h, __nv_bfloat16& l) {
    h = __float2bfloat16(a);
    l = __float2bfloat16(a - __bfloat162float(h));
}

#define MMA_BF16(c0,c1,c2,c3,a0,a1,a2,a3,b0,b1)                              \
    asm volatile("mma.sync.aligned.m16n8k16.row.col.f32.bf16.bf16.f32 "      \
        "{%0,%1,%2,%3}, {%4,%5,%6,%7}, {%8,%9}, {%0,%1,%2,%3};"              \
        : "+f"(c0), "+f"(c1), "+f"(c2), "+f"(c3)                             \
        : "r"(a0), "r"(a1), "r"(a2), "r"(a3), "r"(b0), "r"(b1))

// ===========================================================================
// Kernel 0: weight conversion.  Wfc -> g_Wfch/l (padded to 224 rows, zeros),
// [Wl;Wm;Ws] -> g_Wph/l (768 rows, concat), biases -> g_bias.
// ===========================================================================
__global__ void conv_w_kernel(const float* __restrict__ Wfc,
                              const float* __restrict__ Wl,
                              const float* __restrict__ Wm,
                              const float* __restrict__ Ws,
                              const float* __restrict__ bl,
                              const float* __restrict__ bm,
                              const float* __restrict__ bsv)
{
    int idx = blockIdx.x * blockDim.x + threadIdx.x;
    const int FC_E = NPAD * C_DIM;       // 172032
    const int P_E  = 768 * C_DIM;        // 589824
    if (idx < FC_E) {
        int row = idx / C_DIM, k = idx % C_DIM;
        float v = (row < NCLS) ? Wfc[(size_t)row * C_DIM + k] : 0.f;
        __nv_bfloat16 h, l; bf16_split(v, h, l);
        g_Wfch[idx] = h; g_Wfcl[idx] = l;
    } else if (idx < FC_E + P_E) {
        int j = idx - FC_E;
        int row = j / C_DIM, k = j % C_DIM;
        float v = (row < 192) ? Wl[(size_t)row * C_DIM + k]
                : (row < 384) ? Wm[(size_t)(row - 192) * C_DIM + k]
                              : Ws[(size_t)(row - 384) * C_DIM + k];
        __nv_bfloat16 h, l; bf16_split(v, h, l);
        g_Wph[j] = h; g_Wpl[j] = l;
    }
    if (idx < 768)
        g_bias[idx] = (idx < 192) ? bl[idx]
                    : (idx < 384) ? bm[idx - 192] : bsv[idx - 384];
}

// ===========================================================================
// Kernel 1: fc GEMM via HMMA bf16x2-split.  logits[12544][224] (f32).
// CTA: 64 rows x 112 cols, 128 thr (4 warps 2Mx2N). K-step 16, 48 steps.
// x converted to bf16 hi/lo in-kernel; W pre-converted.
// smem rows padded to 24 bf16 (48B = 12 words) -> conflict-free frag LDS.
// ===========================================================================
__global__ __launch_bounds__(128, 3)
void fc_mma_kernel(const float* __restrict__ x)
{
    __shared__ __align__(16) __nv_bfloat16 sxh[64 * 24], sxl[64 * 24];
    __shared__ __align__(16) __nv_bfloat16 swh[112 * 24], swl[112 * 24];

    const int tid = threadIdx.x, lane = tid & 31, warp = tid >> 5;
    const int g = lane >> 2, t = lane & 3;
    const int wm = warp >> 1, wn = warp & 1;
    const int m0 = blockIdx.x * 64, n0 = blockIdx.y * 112;

    // x fill mapping: thread -> (row = tid>>1, 2 float4 at cols (tid&1)*8)
    const int xrow = tid >> 1, xq = tid & 1;
    const float4* xp = (const float4*)(x + (size_t)(m0 + xrow) * C_DIM) + xq * 2;

    float acc[2][7][4];
#pragma unroll
    for (int i = 0; i < 2; i++)
#pragma unroll
        for (int j = 0; j < 7; j++)
#pragma unroll
            for (int q = 0; q < 4; q++) acc[i][j][q] = 0.f;

    // prefetch tile 0
    float4 xr0 = xp[0], xr1 = xp[1];
    uint4 wr[4];
#pragma unroll
    for (int it = 0; it < 4; it++) {
        int idx = tid + it * 128;
        if (idx < 448) {
            const __nv_bfloat16* Wsrc = (idx >= 224) ? g_Wfcl : g_Wfch;
            int r2 = (idx >= 224) ? idx - 224 : idx;
            int row = r2 >> 1, half = r2 & 1;
            wr[it] = *(const uint4*)&Wsrc[(size_t)(n0 + row) * C_DIM + half * 8];
        }
    }

    for (int step = 0; step < 48; step++) {
        __syncthreads();
        // ---- store x tile (convert f32 -> bf16 hi/lo, packed uint4) ----
        {
            __nv_bfloat162 h01 = __floats2bfloat162_rn(xr0.x, xr0.y);
            __nv_bfloat162 h23 = __floats2bfloat162_rn(xr0.z, xr0.w);
            __nv_bfloat162 h45 = __floats2bfloat162_rn(xr1.x, xr1.y);
            __nv_bfloat162 h67 = __floats2bfloat162_rn(xr1.z, xr1.w);
            float2 f01 = __bfloat1622float2(h01), f23 = __bfloat1622float2(h23);
            float2 f45 = __bfloat1622float2(h45), f67 = __bfloat1622float2(h67);
            __nv_bfloat162 l01 = __floats2bfloat162_rn(xr0.x - f01.x, xr0.y - f01.y);
            __nv_bfloat162 l23 = __floats2bfloat162_rn(xr0.z - f23.x, xr0.w - f23.y);
            __nv_bfloat162 l45 = __floats2bfloat162_rn(xr1.x - f45.x, xr1.y - f45.y);
            __nv_bfloat162 l67 = __floats2bfloat162_rn(xr1.z - f67.x, xr1.w - f67.y);
            *(uint4*)&sxh[xrow * 24 + xq * 8] =
                make_uint4(b2u(h01), b2u(h23), b2u(h45), b2u(h67));
            *(uint4*)&sxl[xrow * 24 + xq * 8] =
                make_uint4(b2u(l01), b2u(l23), b2u(l45), b2u(l67));
        }
        // ---- store W tile ----
#pragma unroll
        for (int it = 0; it < 4; it++) {
            int idx = tid + it * 128;
            if (idx < 448) {
                __nv_bfloat16* dst = (idx >= 224) ? swl : swh;
                int r2 = (idx >= 224) ? idx - 224 : idx;
                int row = r2 >> 1, half = r2 & 1;
                *(uint4*)&dst[row * 24 + half * 8] = wr[it];
            }
        }
        __syncthreads();

        // ---- prefetch next tile ----
        if (step < 47) {
            int k0 = (step + 1) * 16;
            xr0 = xp[k0 / 4];
            xr1 = xp[k0 / 4 + 1];
#pragma unroll
            for (int it = 0; it < 4; it++) {
                int idx = tid + it * 128;
                if (idx < 448) {
                    const __nv_bfloat16* Wsrc = (idx >= 224) ? g_Wfcl : g_Wfch;
                    int r2 = (idx >= 224) ? idx - 224 : idx;
                    int row = r2 >> 1, half = r2 & 1;
                    wr[it] = *(const uint4*)&Wsrc[(size_t)(n0 + row) * C_DIM + k0 + half * 8];
                }
            }
        }

        // ---- MMA ----
        uint ah[2][4], al[2][4];
#pragma unroll
        for (int i = 0; i < 2; i++) {
            int rb = (wm * 32 + i * 16 + g) * 24 + t * 2;
            ah[i][0] = *(uint*)&sxh[rb];
            ah[i][1] = *(uint*)&sxh[rb + 8 * 24];
            ah[i][2] = *(uint*)&sxh[rb + 8];
            ah[i][3] = *(uint*)&sxh[rb + 8 * 24 + 8];
            al[i][0] = *(uint*)&sxl[rb];
            al[i][1] = *(uint*)&sxl[rb + 8 * 24];
            al[i][2] = *(uint*)&sxl[rb + 8];
            al[i][3] = *(uint*)&sxl[rb + 8 * 24 + 8];
        }
#pragma unroll
        for (int j = 0; j < 7; j++) {
            int bb = (wn * 56 + j * 8 + g) * 24 + t * 2;
            uint bh0 = *(uint*)&swh[bb], bh1 = *(uint*)&swh[bb + 8];
            uint bl0 = *(uint*)&swl[bb], bl1 = *(uint*)&swl[bb + 8];
#pragma unroll
            for (int i = 0; i < 2; i++) {
                MMA_BF16(acc[i][j][0], acc[i][j][1], acc[i][j][2], acc[i][j][3],
                         ah[i][0], ah[i][1], ah[i][2], ah[i][3], bh0, bh1);
                MMA_BF16(acc[i][j][0], acc[i][j][1], acc[i][j][2], acc[i][j][3],
                         ah[i][0], ah[i][1], ah[i][2], ah[i][3], bl0, bl1);
                MMA_BF16(acc[i][j][0], acc[i][j][1], acc[i][j][2], acc[i][j][3],
                         al[i][0], al[i][1], al[i][2], al[i][3], bh0, bh1);
            }
        }
    }

    // ---- epilogue: store logits f32 ----
#pragma unroll
    for (int i = 0; i < 2; i++)
#pragma unroll
        for (int j = 0; j < 7; j++) {
            int row = m0 + wm * 32 + i * 16 + g;
            int col = n0 + wn * 56 + j * 8 + t * 2;
            *(float2*)&g_logits[(size_t)row * NPAD + col] =
                make_float2(acc[i][j][0], acc[i][j][1]);
            *(float2*)&g_logits[(size_t)(row + 8) * NPAD + col] =
                make_float2(acc[i][j][2], acc[i][j][3]);
        }
}

// ===========================================================================
// Kernel 2: per-row maxprob = 1/sum(exp(l - lmax)) over 200 valid cols.
// One warp per row; 8 rows per 256-thread block.
// ===========================================================================
__global__ void rowred_kernel(const float* __restrict__ bfc)
{
    int r = blockIdx.x * 8 + (threadIdx.x >> 5);
    int lane = threadIdx.x & 31;
    float v[7];
    float mx = -1e30f;
#pragma unroll
    for (int i = 0; i < 7; i++) {
        int col = i * 32 + lane;
        bool ok = col < NCLS;
        v[i] = ok ? (g_logits[(size_t)r * NPAD + col] + bfc[col]) : -1e30f;
        mx = fmaxf(mx, v[i]);
    }
#pragma unroll
    for (int off = 16; off > 0; off >>= 1)
        mx = fmaxf(mx, __shfl_xor_sync(0xffffffffu, mx, off));
    float s = 0.f;
#pragma unroll
    for (int i = 0; i < 7; i++) s += expf(v[i] - mx);   // invalid -> exp(-inf)=0
#pragma unroll
    for (int off = 16; off > 0; off >>= 1)
        s += __shfl_xor_sync(0xffffffffu, s, off);
    if (lane == 0) g_maxprob[r] = 1.f / s;
}

// ===========================================================================
// Kernel 3: part_logits (8x8 mean-pool, stride 3, pad 2) * mask -> argmax
// ===========================================================================
__global__ void sel_kernel(const float* __restrict__ mask)
{
    int b = blockIdx.x;
    __shared__ float vals[81];
    int p = threadIdx.x;
    if (p < 81) {
        int oy = p / 9, ox = p % 9;
        float s = 0.f;
        for (int i = 0; i < 8; i++) {
            int h = oy * 3 - 2 + i;
            if (h < 0 || h >= 28) continue;
            for (int j = 0; j < 8; j++) {
                int w = ox * 3 - 2 + j;
                if (w < 0 || w >= 28) continue;
                s += g_maxprob[b * 784 + h * 28 + w];
            }
        }
        vals[p] = mask[b * 81 + p] * (s * (1.f / 64.f));
    }
    __syncthreads();
    if (p == 0) {
        float best = vals[0];
        int bi = 0;
        for (int q = 1; q < 81; q++)
            if (vals[q] > best) { best = vals[q]; bi = q; }
        g_sel[b] = bi;
    }
}

// ===========================================================================
// Kernel 4: gather selected patches (fp32 bilinear) -> bf16 hi/lo A matrices
// ===========================================================================
__global__ void gather_kernel(const float* __restrict__ x)
{
    int p    = blockIdx.x;
    int b    = blockIdx.y;
    int part = blockIdx.z;
    int sel  = g_sel[b];
    int oy = sel / 9, ox = sel % 9;
    int i = p >> 3, j = p & 7;

    const float* xb = x + (size_t)b * 784 * C_DIM;
    __nv_bfloat16* oh = &g_Ah[part][(size_t)(b * 64 + p) * C_DIM];
    __nv_bfloat16* ol = &g_Al[part][(size_t)(b * 64 + p) * C_DIM];

    if (part == 0) {
        int h = oy * 3 - 2 + i, w = ox * 3 - 2 + j;
        bool ok = (h >= 0 && h < 28 && w >= 0 && w < 28);
        const float* src = xb + (size_t)(ok ? (h * 28 + w) : 0) * C_DIM;
        for (int c = threadIdx.x; c < C_DIM; c += blockDim.x) {
            float v = ok ? src[c] : 0.f;
            __nv_bfloat16 hh, ll; bf16_split(v, hh, ll);
            oh[c] = hh; ol[c] = ll;
        }
    } else {
        int   n, basepad;
        float scale, offs;
        if (part == 1) { n = 6; basepad = 1; scale = 0.75f; offs = -0.125f; }
        else           { n = 4; basepad = 0; scale = 0.5f;  offs = -0.25f;  }
        float sy = fminf(fmaxf(scale * i + offs, 0.f), (float)(n - 1));
        float sx = fminf(fmaxf(scale * j + offs, 0.f), (float)(n - 1));
        int iy0 = (int)sy; float fy = sy - iy0; int iy1 = min(iy0 + 1, n - 1);
        int ix0 = (int)sx; float fx = sx - ix0; int ix1 = min(ix0 + 1, n - 1);
        int hb = oy * 3 - basepad, wb = ox * 3 - basepad;
        int h0 = hb + iy0, h1 = hb + iy1, w0 = wb + ix0, w1 = wb + ix1;
        bool okh0 = (h0 >= 0 && h0 < 28), okh1 = (h1 >= 0 && h1 < 28);
        bool okw0 = (w0 >= 0 && w0 < 28), okw1 = (w1 >= 0 && w1 < 28);
        bool ok00 = okh0 && okw0, ok01 = okh0 && okw1;
        bool ok10 = okh1 && okw0, ok11 = okh1 && okw1;
        size_t o00 = (size_t)(ok00 ? (h0 * 28 + w0) : 0) * C_DIM;
        size_t o01 = (size_t)(ok01 ? (h0 * 28 + w1) : 0) * C_DIM;
        size_t o10 = (size_t)(ok10 ? (h1 * 28 + w0) : 0) * C_DIM;
        size_t o11 = (size_t)(ok11 ? (h1 * 28 + w1) : 0) * C_DIM;
        for (int c = threadIdx.x; c < C_DIM; c += blockDim.x) {
            float v00 = ok00 ? xb[o00 + c] : 0.f;
            float v01 = ok01 ? xb[o01 + c] : 0.f;
            float v10 = ok10 ? xb[o10 + c] : 0.f;
            float v11 = ok11 ? xb[o11 + c] : 0.f;
            float v = (1.f - fy) * ((1.f - fx) * v00 + fx * v01)
                    +        fy  * ((1.f - fx) * v10 + fx * v11);
            __nv_bfloat16 hh, ll; bf16_split(v, hh, ll);
            oh[c] = hh; ol[c] = ll;
        }
    }
}

// ===========================================================================
// Kernel 5: parts GEMM via HMMA bf16x2-split.  out[1024][768] + bias.
// CTA: 32 rows x 64 cols; grid (32, 12).  Concat weight layout.
// ===========================================================================
__global__ __launch_bounds__(128, 4)
void parts_mma_kernel(float* __restrict__ out)
{
    __shared__ __align__(16) __nv_bfloat16 sah[32 * 24], sal[32 * 24];
    __shared__ __align__(16) __nv_bfloat16 swh[64 * 24], swl[64 * 24];

    const int tid = threadIdx.x, lane = tid & 31, warp = tid >> 5;
    const int g = lane >> 2, t = lane & 3;
    const int wm = warp >> 1, wn = warp & 1;
    const int m0 = blockIdx.x * 32;
    const int n0c = blockIdx.y * 64;
    const int part = (n0c < 192) ? 0 : (n0c < 384) ? 1 : 2;
    const __nv_bfloat16* Ah = g_Ah[part];
    const __nv_bfloat16* Al = g_Al[part];

    float acc[4][4];
#pragma unroll
    for (int j = 0; j < 4; j++)
#pragma unroll
        for (int q = 0; q < 4; q++) acc[j][q] = 0.f;

    // A fill: 128 uint4; tid<64 -> hi, else lo; row=(tid&63)>>1, half=tid&1
    const int aprec = tid >> 6, arr = tid & 63;
    const int arow = arr >> 1, ahalf = arr & 1;
    const __nv_bfloat16* Asrc =
        (aprec ? Al : Ah) + (size_t)(m0 + arow) * C_DIM + ahalf * 8;
    // W fill: 2 uint4; it=0 hi, it=1 lo; row=tid>>1, half=tid&1
    const size_t woff = (size_t)(n0c + (tid >> 1)) * C_DIM + (tid & 1) * 8;

    uint4 ar = *(const uint4*)&Asrc[0];
    uint4 wr0 = *(const uint4*)&g_Wph[woff];
    uint4 wr1 = *(const uint4*)&g_Wpl[woff];

    for (int step = 0; step < 48; step++) {
        __syncthreads();
        *(uint4*)&(aprec ? sal : sah)[arow * 24 + ahalf * 8] = ar;
        *(uint4*)&swh[(tid >> 1) * 24 + (tid & 1) * 8] = wr0;
        *(uint4*)&swl[(tid >> 1) * 24 + (tid & 1) * 8] = wr1;
        __syncthreads();

        if (step < 47) {
            int k0 = (step + 1) * 16;
            ar  = *(const uint4*)&Asrc[k0];
            wr0 = *(const uint4*)&g_Wph[woff + k0];
            wr1 = *(const uint4*)&g_Wpl[woff + k0];
        }

        uint ah[4], al[4];
        {
            int rb = (wm * 16 + g) * 24 + t * 2;
            ah[0] = *(uint*)&sah[rb];
            ah[1] = *(uint*)&sah[rb + 8 * 24];
            ah[2] = *(uint*)&sah[rb + 8];
            ah[3] = *(uint*)&sah[rb + 8 * 24 + 8];
            al[0] = *(uint*)&sal[rb];
            al[1] = *(uint*)&sal[rb + 8 * 24];
            al[2] = *(uint*)&sal[rb + 8];
            al[3] = *(uint*)&sal[rb + 8 * 24 + 8];
        }
#pragma unroll
        for (int j = 0; j < 4; j++) {
            int bb = (wn * 32 + j * 8 + g) * 24 + t * 2;
            uint bh0 = *(uint*)&swh[bb], bh1 = *(uint*)&swh[bb + 8];
            uint bl0 = *(uint*)&swl[bb], bl1 = *(uint*)&swl[bb + 8];
            MMA_BF16(acc[j][0], acc[j][1], acc[j][2], acc[j][3],
                     ah[0], ah[1], ah[2], ah[3], bh0, bh1);
            MMA_BF16(acc[j][0], acc[j][1], acc[j][2], acc[j][3],
                     ah[0], ah[1], ah[2], ah[3], bl0, bl1);
            MMA_BF16(acc[j][0], acc[j][1], acc[j][2], acc[j][3],
                     al[0], al[1], al[2], al[3], bh0, bh1);
        }
    }

#pragma unroll
    for (int j = 0; j < 4; j++) {
        int m   = m0 + wm * 16 + g;
        int col = n0c + wn * 32 + j * 8 + t * 2;
        float2 bc = *(float2*)&g_bias[col];
        *(float2*)&out[(size_t)m * 768 + col] =
            make_float2(acc[j][0] + bc.x, acc[j][1] + bc.y);
        *(float2*)&out[(size_t)(m + 8) * 768 + col] =
            make_float2(acc[j][2] + bc.x, acc[j][3] + bc.y);
    }
}

// ===========================================================================
// Kernel 6: image patch gather (128x128 @ stride 48, pad 32) + bilinear 224.
// ===========================================================================
__global__ void image_kernel(const float* __restrict__ img, float* __restrict__ out)
{
    int idx = blockIdx.x * blockDim.x + threadIdx.x;
    if (idx >= IMG_OUT_ELEMS) return;
    int ox = idx % 224;
    int oy = (idx / 224) % 224;
    int ch = (idx / (224 * 224)) % 3;
    int b  = idx / (3 * 224 * 224);

    int sel = g_sel[b];
    int r0 = (sel / 9) * 48 - 32;
    int c0 = (sel % 9) * 48 - 32;

    const float s = 128.f / 224.f;
    float sy = fminf(fmaxf((oy + 0.5f) * s - 0.5f, 0.f), 127.f);
    float sx = fminf(fmaxf((ox + 0.5f) * s - 0.5f, 0.f), 127.f);
    int py0 = (int)sy; float fy = sy - py0; int py1 = min(py0 + 1, 127);
    int px0 = (int)sx; float fx = sx - px0; int px1 = min(px0 + 1, 127);

    const float* ib = img + (size_t)(b * 3 + ch) * 448 * 448;
    int gy0 = r0 + py0, gy1 = r0 + py1, gx0 = c0 + px0, gx1 = c0 + px1;
    bool oky0 = (gy0 >= 0 && gy0 < 448), oky1 = (gy1 >= 0 && gy1 < 448);
    bool okx0 = (gx0 >= 0 && gx0 < 448), okx1 = (gx1 >= 0 && gx1 < 448);
    float v00 = (oky0 && okx0) ? ib[gy0 * 448 + gx0] : 0.f;
    float v01 = (oky0 && okx1) ? ib[gy0 * 448 + gx1] : 0.f;
    float v10 = (oky1 && okx0) ? ib[gy1 * 448 + gx0] : 0.f;
    float v11 = (oky1 && okx1) ? ib[gy1 * 448 + gx1] : 0.f;

    out[idx] = (1.f - fy) * ((1.f - fx) * v00 + fx * v01)
             +        fy  * ((1.f - fx) * v10 + fx * v11);
}

// ===========================================================================
extern "C" void kernel_launch(void* const* d_in, const int* in_sizes, int n_in,
                              void* d_out, int out_size)
{
    const float* x    = (const float*)d_in[0];
    const float* mask = (const float*)d_in[1];
    const float* img  = (const float*)d_in[2];
    const float* Wfc  = (const float*)d_in[3];
    const float* bfc  = (const float*)d_in[4];
    const float* Wl   = (const float*)d_in[5];
    const float* bl   = (const float*)d_in[6];
    const float* Wm   = (const float*)d_in[7];
    const float* bm   = (const float*)d_in[8];
    const float* Ws   = (const float*)d_in[9];
    const float* bsv  = (const float*)d_in[10];

    float* out_ff  = (float*)d_out;                 // [16,64,768]
    float* out_img = (float*)d_out + FF_ELEMS;      // [16,3,224,224]

    conv_w_kernel<<<(992 * 768 + 255) / 256, 256>>>(Wfc, Wl, Wm, Ws, bl, bm, bsv);
    {
        dim3 g(M_ROWS / 64, 2);
        fc_mma_kernel<<<g, 128>>>(x);
    }
    rowred_kernel<<<M_ROWS / 8, 256>>>(bfc);
    sel_kernel<<<BATCH, 128>>>(mask);
    {
        dim3 g(64, BATCH, 3);
        gather_kernel<<<g, 256>>>(x);
    }
    {
        dim3 g(32, 12);
        parts_mma_kernel<<<g, 128>>>(out_ff);
    }
    image_kernel<<<(IMG_OUT_ELEMS + 255) / 256, 256>>>(img, out_img);
}

// round 6
// speedup vs baseline: 2.9334x; 1.1146x over previous
#include <cuda_runtime.h>
#include <cuda_bf16.h>
#include <math.h>

typedef unsigned int uint;

#define C_DIM   768
#define NCLS    200
#define BATCH   16
#define M_ROWS  (BATCH * 784)   // 12544
#define NPAD    224
#define FF_ELEMS (BATCH * 64 * 768)              // 786432
#define IMG_OUT_ELEMS (BATCH * 3 * 224 * 224)    // 2408448

// ---------------- scratch (device globals; no runtime alloc allowed) -------
__device__ float g_maxprob[M_ROWS];
__device__ int   g_sel[BATCH];
__device__ __align__(16) __nv_bfloat16 g_Wfch[NPAD * C_DIM];
__device__ __align__(16) __nv_bfloat16 g_Wfcl[NPAD * C_DIM];
__device__ __align__(16) __nv_bfloat16 g_Wph[768 * C_DIM];
__device__ __align__(16) __nv_bfloat16 g_Wpl[768 * C_DIM];
__device__ __align__(16) float g_bias[768];
__device__ __align__(16) __nv_bfloat16 g_Ah[3][1024 * C_DIM];
__device__ __align__(16) __nv_bfloat16 g_Al[3][1024 * C_DIM];

__device__ __forceinline__ uint b2u(__nv_bfloat162 v) {
    return *reinterpret_cast<uint*>(&v);
}
__device__ __forceinline__ void bf16_split(float a, __nv_bfloat16& h, __nv_bfloat16& l) {
    h = __float2bfloat16(a);
    l = __float2bfloat16(a - __bfloat162float(h));
}
__device__ __forceinline__ uint smem_u32(const void* p) {
    return (uint)__cvta_generic_to_shared(p);
}

#define MMA_BF16(c0,c1,c2,c3,a0,a1,a2,a3,b0,b1)                              \
    asm volatile("mma.sync.aligned.m16n8k16.row.col.f32.bf16.bf16.f32 "      \
        "{%0,%1,%2,%3}, {%4,%5,%6,%7}, {%8,%9}, {%0,%1,%2,%3};"              \
        : "+f"(c0), "+f"(c1), "+f"(c2), "+f"(c3)                             \
        : "r"(a0), "r"(a1), "r"(a2), "r"(a3), "r"(b0), "r"(b1))

#define LDSM_X4(r0,r1,r2,r3,addr)                                            \
    asm volatile("ldmatrix.sync.aligned.m8n8.x4.shared.b16 {%0,%1,%2,%3}, [%4];" \
        : "=r"(r0), "=r"(r1), "=r"(r2), "=r"(r3) : "r"(addr))

#define CP_ASYNC16(dst, src) \
    asm volatile("cp.async.cg.shared.global [%0], [%1], 16;" :: "r"(dst), "l"(src))
#define CP_COMMIT() asm volatile("cp.async.commit_group;")
#define CP_WAIT0()  asm volatile("cp.async.wait_group 0;")

// ===========================================================================
// Kernel 0: weight conversion (bf16 hi/lo split) + bias concat.
// ===========================================================================
__global__ void conv_w_kernel(const float* __restrict__ Wfc,
                              const float* __restrict__ Wl,
                              const float* __restrict__ Wm,
                              const float* __restrict__ Ws,
                              const float* __restrict__ bl,
                              const float* __restrict__ bm,
                              const float* __restrict__ bsv)
{
    int idx = blockIdx.x * blockDim.x + threadIdx.x;
    const int FC_E = NPAD * C_DIM;       // 172032
    const int P_E  = 768 * C_DIM;        // 589824
    if (idx < FC_E) {
        int row = idx / C_DIM, k = idx % C_DIM;
        float v = (row < NCLS) ? Wfc[(size_t)row * C_DIM + k] : 0.f;
        __nv_bfloat16 h, l; bf16_split(v, h, l);
        g_Wfch[idx] = h; g_Wfcl[idx] = l;
    } else if (idx < FC_E + P_E) {
        int j = idx - FC_E;
        int row = j / C_DIM, k = j % C_DIM;
        float v = (row < 192) ? Wl[(size_t)row * C_DIM + k]
                : (row < 384) ? Wm[(size_t)(row - 192) * C_DIM + k]
                              : Ws[(size_t)(row - 384) * C_DIM + k];
        __nv_bfloat16 h, l; bf16_split(v, h, l);
        g_Wph[j] = h; g_Wpl[j] = l;
    }
    if (idx < 768)
        g_bias[idx] = (idx < 192) ? bl[idx]
                    : (idx < 384) ? bm[idx - 192] : bsv[idx - 384];
}

// ===========================================================================
// Kernel 1: fc GEMM (HMMA bf16 3-chain split) + fused softmax-max reduce.
// CTA: 64 rows x 224 cols (all N). 256 thr = 8 warps (wm=warp&3 rows wm*16,
// wn=warp>>2 cols wn*112). BK=16, 48 steps, double-buffered, ldmatrix frags,
// cp.async W tiles. Epilogue: maxprob = 1/sum exp(l-lmax), no logits buffer.
// ===========================================================================
#define FC_XBUF_B  (64 * 24 * 2)      // bytes per X buffer (per precision)
#define FC_WBUF_B  (224 * 24 * 2)
#define FC_SMEM    (2 * 2 * FC_XBUF_B + 2 * 2 * FC_WBUF_B + 2 * 2 * 64 * 4)

__global__ __launch_bounds__(256, 2)
void fc_mma_kernel(const float* __restrict__ x, const float* __restrict__ bfc)
{
    extern __shared__ __align__(16) char sm_raw[];
    __nv_bfloat16* sxh = (__nv_bfloat16*)sm_raw;                    // [2] bufs
    __nv_bfloat16* sxl = (__nv_bfloat16*)(sm_raw + 2 * FC_XBUF_B);
    __nv_bfloat16* swh = (__nv_bfloat16*)(sm_raw + 4 * FC_XBUF_B);
    __nv_bfloat16* swl = (__nv_bfloat16*)(sm_raw + 4 * FC_XBUF_B + 2 * FC_WBUF_B);
    float* red = (float*)(sm_raw + 4 * FC_XBUF_B + 4 * FC_WBUF_B);  // [2][2][64]

    const int tid = threadIdx.x, lane = tid & 31, warp = tid >> 5;
    const int g = lane >> 2, t = lane & 3;
    const int wm = warp & 3, wn = warp >> 2;
    const int m0 = blockIdx.x * 64;

    // ---- X fill mapping: thread -> (row = tid>>2, 4 floats at k (tid&3)*4)
    const int xrow = tid >> 2, xkq = tid & 3;
    const float4* xp = (const float4*)(x + (size_t)(m0 + xrow) * C_DIM) + xkq;
    char* sxh_dst = (char*)(sxh + xrow * 24 + xkq * 4);
    char* sxl_dst = (char*)(sxl + xrow * 24 + xkq * 4);

    // ---- W fill mapping: 896 16B chunks/step, cp.async, 4 per thread
    const __nv_bfloat16* wsrc[4];
    uint wdst[4];
    bool wok[4];
#pragma unroll
    for (int it = 0; it < 4; it++) {
        int idx = tid + it * 256;
        wok[it] = idx < 896;
        int prec = idx >= 448;
        int rr = prec ? idx - 448 : idx;
        int row = rr >> 1, half = rr & 1;
        wsrc[it] = (prec ? g_Wfcl : g_Wfch) + (size_t)row * C_DIM + half * 8;
        wdst[it] = smem_u32((prec ? swl : swh) + row * 24 + half * 8);
    }

    // ---- ldmatrix lane base addresses (buffer 0)
    const uint a_base  = (uint)((wm * 16 + (lane & 15)) * 24 + (lane >> 4) * 8) * 2;
    const uint ah_addr = smem_u32(sxh) + a_base;
    const uint al_addr = smem_u32(sxl) + a_base;
    const uint b_base  = (uint)((wn * 112 + ((lane >> 4) & 1) * 8 + (lane & 7)) * 24
                                + ((lane >> 3) & 1) * 8) * 2;
    const uint bh_addr = smem_u32(swh) + b_base;
    const uint bl_addr = smem_u32(swl) + b_base;

    float acc[14][4];
#pragma unroll
    for (int j = 0; j < 14; j++)
#pragma unroll
        for (int q = 0; q < 4; q++) acc[j][q] = 0.f;

    // ---- prologue: tile 0
    float4 xr = xp[0];
#pragma unroll
    for (int it = 0; it < 4; it++)
        if (wok[it]) CP_ASYNC16(wdst[it], wsrc[it]);
    CP_COMMIT();
    {
        __nv_bfloat162 h01 = __floats2bfloat162_rn(xr.x, xr.y);
        __nv_bfloat162 h23 = __floats2bfloat162_rn(xr.z, xr.w);
        float2 f01 = __bfloat1622float2(h01), f23 = __bfloat1622float2(h23);
        *(uint2*)sxh_dst = make_uint2(b2u(h01), b2u(h23));
        *(uint2*)sxl_dst = make_uint2(
            b2u(__floats2bfloat162_rn(xr.x - f01.x, xr.y - f01.y)),
            b2u(__floats2bfloat162_rn(xr.z - f23.x, xr.w - f23.y)));
    }
    CP_WAIT0();
    __syncthreads();

    for (int step = 0; step < 48; step++) {
        const int buf = step & 1;
        const uint xoff  = (uint)buf * FC_XBUF_B;          // byte offsets
        const uint woff  = (uint)buf * FC_WBUF_B;
        const uint nxoff = (uint)(buf ^ 1) * FC_XBUF_B;
        const uint nwoff = (uint)(buf ^ 1) * FC_WBUF_B;

        if (step < 47) {
            xr = xp[(step + 1) * 4];
#pragma unroll
            for (int it = 0; it < 4; it++)
                if (wok[it]) CP_ASYNC16(wdst[it] + nwoff, wsrc[it] + (step + 1) * 16);
            CP_COMMIT();
        }

        uint ah[4], al[4];
        LDSM_X4(ah[0], ah[1], ah[2], ah[3], ah_addr + xoff);
        LDSM_X4(al[0], al[1], al[2], al[3], al_addr + xoff);
#pragma unroll
        for (int jp = 0; jp < 7; jp++) {
            uint bh[4], bl[4];
            LDSM_X4(bh[0], bh[1], bh[2], bh[3], bh_addr + woff + jp * 768);
            LDSM_X4(bl[0], bl[1], bl[2], bl[3], bl_addr + woff + jp * 768);
            const int j0 = 2 * jp, j1 = j0 + 1;
            MMA_BF16(acc[j0][0], acc[j0][1], acc[j0][2], acc[j0][3],
                     ah[0], ah[1], ah[2], ah[3], bh[0], bh[1]);
            MMA_BF16(acc[j0][0], acc[j0][1], acc[j0][2], acc[j0][3],
                     ah[0], ah[1], ah[2], ah[3], bl[0], bl[1]);
            MMA_BF16(acc[j0][0], acc[j0][1], acc[j0][2], acc[j0][3],
                     al[0], al[1], al[2], al[3], bh[0], bh[1]);
            MMA_BF16(acc[j1][0], acc[j1][1], acc[j1][2], acc[j1][3],
                     ah[0], ah[1], ah[2], ah[3], bh[2], bh[3]);
            MMA_BF16(acc[j1][0], acc[j1][1], acc[j1][2], acc[j1][3],
                     ah[0], ah[1], ah[2], ah[3], bl[2], bl[3]);
            MMA_BF16(acc[j1][0], acc[j1][1], acc[j1][2], acc[j1][3],
                     al[0], al[1], al[2], al[3], bh[2], bh[3]);
        }

        if (step < 47) {
            __nv_bfloat162 h01 = __floats2bfloat162_rn(xr.x, xr.y);
            __nv_bfloat162 h23 = __floats2bfloat162_rn(xr.z, xr.w);
            float2 f01 = __bfloat1622float2(h01), f23 = __bfloat1622float2(h23);
            *(uint2*)(sxh_dst + nxoff) = make_uint2(b2u(h01), b2u(h23));   // FIXED
            *(uint2*)(sxl_dst + nxoff) = make_uint2(                       // FIXED
                b2u(__floats2bfloat162_rn(xr.x - f01.x, xr.y - f01.y)),
                b2u(__floats2bfloat162_rn(xr.z - f23.x, xr.w - f23.y)));
            CP_WAIT0();
        }
        __syncthreads();
    }

    // ---- epilogue: bias + mask, fused row max / sumexp reduce ----
#pragma unroll
    for (int j = 0; j < 14; j++) {
        int col = wn * 112 + j * 8 + t * 2;
        if (col < NCLS) { float b = bfc[col]; acc[j][0] += b; acc[j][2] += b; }
        else            { acc[j][0] = acc[j][2] = -1e30f; }
        if (col + 1 < NCLS) { float b = bfc[col + 1]; acc[j][1] += b; acc[j][3] += b; }
        else                { acc[j][1] = acc[j][3] = -1e30f; }
    }
    const int r0 = wm * 16 + g, r1 = r0 + 8;
    float mx0 = -1e30f, mx1 = -1e30f;
#pragma unroll
    for (int j = 0; j < 14; j++) {
        mx0 = fmaxf(mx0, fmaxf(acc[j][0], acc[j][1]));
        mx1 = fmaxf(mx1, fmaxf(acc[j][2], acc[j][3]));
    }
#pragma unroll
    for (int off = 1; off <= 2; off <<= 1) {
        mx0 = fmaxf(mx0, __shfl_xor_sync(0xffffffffu, mx0, off));
        mx1 = fmaxf(mx1, __shfl_xor_sync(0xffffffffu, mx1, off));
    }
    if (t == 0) { red[wn * 64 + r0] = mx0; red[wn * 64 + r1] = mx1; }
    __syncthreads();
    const float rm0 = fmaxf(red[r0], red[64 + r0]);
    const float rm1 = fmaxf(red[r1], red[64 + r1]);
    float s0 = 0.f, s1 = 0.f;
#pragma unroll
    for (int j = 0; j < 14; j++) {
        s0 += expf(acc[j][0] - rm0) + expf(acc[j][1] - rm0);
        s1 += expf(acc[j][2] - rm1) + expf(acc[j][3] - rm1);
    }
#pragma unroll
    for (int off = 1; off <= 2; off <<= 1) {
        s0 += __shfl_xor_sync(0xffffffffu, s0, off);
        s1 += __shfl_xor_sync(0xffffffffu, s1, off);
    }
    if (t == 0) { red[128 + wn * 64 + r0] = s0; red[128 + wn * 64 + r1] = s1; }
    __syncthreads();
    if (wn == 0 && t == 0) {
        g_maxprob[m0 + r0] = 1.f / (red[128 + r0] + red[128 + 64 + r0]);
        g_maxprob[m0 + r1] = 1.f / (red[128 + r1] + red[128 + 64 + r1]);
    }
}

// ===========================================================================
// Kernel 2: part_logits (8x8 mean-pool, stride 3, pad 2) * mask -> argmax
// ===========================================================================
__global__ void sel_kernel(const float* __restrict__ mask)
{
    int b = blockIdx.x;
    __shared__ float map[784];
    __shared__ float vals[81];
    int p = threadIdx.x;
    for (int i = p; i < 784; i += 128) map[i] = g_maxprob[b * 784 + i];
    __syncthreads();
    if (p < 81) {
        int oy = p / 9, ox = p % 9;
        float s = 0.f;
#pragma unroll
        for (int i = 0; i < 8; i++) {
            int h = oy * 3 - 2 + i;
            if (h < 0 || h >= 28) continue;
#pragma unroll
            for (int j = 0; j < 8; j++) {
                int w = ox * 3 - 2 + j;
                if (w < 0 || w >= 28) continue;
                s += map[h * 28 + w];
            }
        }
        vals[p] = mask[b * 81 + p] * (s * (1.f / 64.f));
    }
    __syncthreads();
    if (p == 0) {
        float best = vals[0];
        int bi = 0;
        for (int q = 1; q < 81; q++)
            if (vals[q] > best) { best = vals[q]; bi = q; }
        g_sel[b] = bi;
    }
}

// ===========================================================================
// Kernel 3: gather selected patches (fp32 bilinear) -> bf16 hi/lo A matrices
// ===========================================================================
__global__ void gather_kernel(const float* __restrict__ x)
{
    int p    = blockIdx.x;
    int b    = blockIdx.y;
    int part = blockIdx.z;
    int sel  = g_sel[b];
    int oy = sel / 9, ox = sel % 9;
    int i = p >> 3, j = p & 7;

    const float* xb = x + (size_t)b * 784 * C_DIM;
    __nv_bfloat16* oh = &g_Ah[part][(size_t)(b * 64 + p) * C_DIM];
    __nv_bfloat16* ol = &g_Al[part][(size_t)(b * 64 + p) * C_DIM];

    if (part == 0) {
        int h = oy * 3 - 2 + i, w = ox * 3 - 2 + j;
        bool ok = (h >= 0 && h < 28 && w >= 0 && w < 28);
        const float* src = xb + (size_t)(ok ? (h * 28 + w) : 0) * C_DIM;
        for (int c = threadIdx.x; c < C_DIM; c += blockDim.x) {
            float v = ok ? src[c] : 0.f;
            __nv_bfloat16 hh, ll; bf16_split(v, hh, ll);
            oh[c] = hh; ol[c] = ll;
        }
    } else {
        int   n, basepad;
        float scale, offs;
        if (part == 1) { n = 6; basepad = 1; scale = 0.75f; offs = -0.125f; }
        else           { n = 4; basepad = 0; scale = 0.5f;  offs = -0.25f;  }
        float sy = fminf(fmaxf(scale * i + offs, 0.f), (float)(n - 1));
        float sx = fminf(fmaxf(scale * j + offs, 0.f), (float)(n - 1));
        int iy0 = (int)sy; float fy = sy - iy0; int iy1 = min(iy0 + 1, n - 1);
        int ix0 = (int)sx; float fx = sx - ix0; int ix1 = min(ix0 + 1, n - 1);
        int hb = oy * 3 - basepad, wb = ox * 3 - basepad;
        int h0 = hb + iy0, h1 = hb + iy1, w0 = wb + ix0, w1 = wb + ix1;
        bool okh0 = (h0 >= 0 && h0 < 28), okh1 = (h1 >= 0 && h1 < 28);
        bool okw0 = (w0 >= 0 && w0 < 28), okw1 = (w1 >= 0 && w1 < 28);
        bool ok00 = okh0 && okw0, ok01 = okh0 && okw1;
        bool ok10 = okh1 && okw0, ok11 = okh1 && okw1;
        size_t o00 = (size_t)(ok00 ? (h0 * 28 + w0) : 0) * C_DIM;
        size_t o01 = (size_t)(ok01 ? (h0 * 28 + w1) : 0) * C_DIM;
        size_t o10 = (size_t)(ok10 ? (h1 * 28 + w0) : 0) * C_DIM;
        size_t o11 = (size_t)(ok11 ? (h1 * 28 + w1) : 0) * C_DIM;
        for (int c = threadIdx.x; c < C_DIM; c += blockDim.x) {
            float v00 = ok00 ? xb[o00 + c] : 0.f;
            float v01 = ok01 ? xb[o01 + c] : 0.f;
            float v10 = ok10 ? xb[o10 + c] : 0.f;
            float v11 = ok11 ? xb[o11 + c] : 0.f;
            float v = (1.f - fy) * ((1.f - fx) * v00 + fx * v01)
                    +        fy  * ((1.f - fx) * v10 + fx * v11);
            __nv_bfloat16 hh, ll; bf16_split(v, hh, ll);
            oh[c] = hh; ol[c] = ll;
        }
    }
}

// ===========================================================================
// Kernel 4: parts GEMM (HMMA 3-chain).  BM=64, BN=64, grid(16,12), 256 thr.
// ===========================================================================
#define P_BUF (64 * 24)   // bf16 elems per tile buffer (per matrix, per prec)

__global__ __launch_bounds__(256, 3)
void parts_mma_kernel(float* __restrict__ out)
{
    __shared__ __align__(16) __nv_bfloat16 sah[2][P_BUF], sal[2][P_BUF];
    __shared__ __align__(16) __nv_bfloat16 swh[2][P_BUF], swl[2][P_BUF];

    const int tid = threadIdx.x, lane = tid & 31, warp = tid >> 5;
    const int g = lane >> 2, t = lane & 3;
    const int wm = warp & 3, wn = warp >> 2;
    const int m0 = blockIdx.x * 64;
    const int n0c = blockIdx.y * 64;
    const int part = (n0c < 192) ? 0 : (n0c < 384) ? 1 : 2;

    const int prec = tid >= 128, rr = tid & 127;
    const int frow = rr >> 1, fhalf = rr & 1;
    const __nv_bfloat16* asrc =
        (prec ? g_Al[part] : g_Ah[part]) + (size_t)(m0 + frow) * C_DIM + fhalf * 8;
    const __nv_bfloat16* wsrc =
        (prec ? g_Wpl : g_Wph) + (size_t)(n0c + frow) * C_DIM + fhalf * 8;
    const uint adst = smem_u32((prec ? sal[0] : sah[0]) + frow * 24 + fhalf * 8);
    const uint wdst = smem_u32((prec ? swl[0] : swh[0]) + frow * 24 + fhalf * 8);

    const uint a_base  = (uint)((wm * 16 + (lane & 15)) * 24 + (lane >> 4) * 8) * 2;
    const uint ah_addr = smem_u32(sah[0]) + a_base;
    const uint al_addr = smem_u32(sal[0]) + a_base;
    const uint b_base  = (uint)((wn * 32 + ((lane >> 4) & 1) * 8 + (lane & 7)) * 24
                                + ((lane >> 3) & 1) * 8) * 2;
    const uint bh_addr = smem_u32(swh[0]) + b_base;
    const uint bl_addr = smem_u32(swl[0]) + b_base;

    float acc[4][4];
#pragma unroll
    for (int j = 0; j < 4; j++)
#pragma unroll
        for (int q = 0; q < 4; q++) acc[j][q] = 0.f;

    CP_ASYNC16(adst, asrc);
    CP_ASYNC16(wdst, wsrc);
    CP_COMMIT();
    CP_WAIT0();
    __syncthreads();

    for (int step = 0; step < 48; step++) {
        const int buf = step & 1;
        const uint off  = (uint)buf * (P_BUF * 2);
        const uint noff = (uint)(buf ^ 1) * (P_BUF * 2);

        if (step < 47) {
            CP_ASYNC16(adst + noff, asrc + (step + 1) * 16);
            CP_ASYNC16(wdst + noff, wsrc + (step + 1) * 16);
            CP_COMMIT();
        }

        uint ah[4], al[4];
        LDSM_X4(ah[0], ah[1], ah[2], ah[3], ah_addr + off);
        LDSM_X4(al[0], al[1], al[2], al[3], al_addr + off);
#pragma unroll
        for (int jp = 0; jp < 2; jp++) {
            uint bh[4], bl[4];
            LDSM_X4(bh[0], bh[1], bh[2], bh[3], bh_addr + off + jp * 768);
            LDSM_X4(bl[0], bl[1], bl[2], bl[3], bl_addr + off + jp * 768);
            const int j0 = 2 * jp, j1 = j0 + 1;
            MMA_BF16(acc[j0][0], acc[j0][1], acc[j0][2], acc[j0][3],
                     ah[0], ah[1], ah[2], ah[3], bh[0], bh[1]);
            MMA_BF16(acc[j0][0], acc[j0][1], acc[j0][2], acc[j0][3],
                     ah[0], ah[1], ah[2], ah[3], bl[0], bl[1]);
            MMA_BF16(acc[j0][0], acc[j0][1], acc[j0][2], acc[j0][3],
                     al[0], al[1], al[2], al[3], bh[0], bh[1]);
            MMA_BF16(acc[j1][0], acc[j1][1], acc[j1][2], acc[j1][3],
                     ah[0], ah[1], ah[2], ah[3], bh[2], bh[3]);
            MMA_BF16(acc[j1][0], acc[j1][1], acc[j1][2], acc[j1][3],
                     ah[0], ah[1], ah[2], ah[3], bl[2], bl[3]);
            MMA_BF16(acc[j1][0], acc[j1][1], acc[j1][2], acc[j1][3],
                     al[0], al[1], al[2], al[3], bh[2], bh[3]);
        }

        if (step < 47) CP_WAIT0();
        __syncthreads();
    }

#pragma unroll
    for (int j = 0; j < 4; j++) {
        int col = n0c + wn * 32 + j * 8 + t * 2;
        int m   = m0 + wm * 16 + g;
        float2 bc = *(float2*)&g_bias[col];
        *(float2*)&out[(size_t)m * 768 + col] =
            make_float2(acc[j][0] + bc.x, acc[j][1] + bc.y);
        *(float2*)&out[(size_t)(m + 8) * 768 + col] =
            make_float2(acc[j][2] + bc.x, acc[j][3] + bc.y);
    }
}

// ===========================================================================
// Kernel 5: image patch gather (128x128 @ stride 48, pad 32) + bilinear 224.
// ===========================================================================
__global__ void image_kernel(const float* __restrict__ img, float* __restrict__ out)
{
    int idx = blockIdx.x * blockDim.x + threadIdx.x;
    if (idx >= IMG_OUT_ELEMS) return;
    int ox = idx % 224;
    int oy = (idx / 224) % 224;
    int ch = (idx / (224 * 224)) % 3;
    int b  = idx / (3 * 224 * 224);

    int sel = g_sel[b];
    int r0 = (sel / 9) * 48 - 32;
    int c0 = (sel % 9) * 48 - 32;

    const float s = 128.f / 224.f;
    float sy = fminf(fmaxf((oy + 0.5f) * s - 0.5f, 0.f), 127.f);
    float sx = fminf(fmaxf((ox + 0.5f) * s - 0.5f, 0.f), 127.f);
    int py0 = (int)sy; float fy = sy - py0; int py1 = min(py0 + 1, 127);
    int px0 = (int)sx; float fx = sx - px0; int px1 = min(px0 + 1, 127);

    const float* ib = img + (size_t)(b * 3 + ch) * 448 * 448;
    int gy0 = r0 + py0, gy1 = r0 + py1, gx0 = c0 + px0, gx1 = c0 + px1;
    bool oky0 = (gy0 >= 0 && gy0 < 448), oky1 = (gy1 >= 0 && gy1 < 448);
    bool okx0 = (gx0 >= 0 && gx0 < 448), okx1 = (gx1 >= 0 && gx1 < 448);
    float v00 = (oky0 && okx0) ? ib[gy0 * 448 + gx0] : 0.f;
    float v01 = (oky0 && okx1) ? ib[gy0 * 448 + gx1] : 0.f;
    float v10 = (oky1 && okx0) ? ib[gy1 * 448 + gx0] : 0.f;
    float v11 = (oky1 && okx1) ? ib[gy1 * 448 + gx1] : 0.f;

    out[idx] = (1.f - fy) * ((1.f - fx) * v00 + fx * v01)
             +        fy  * ((1.f - fx) * v10 + fx * v11);
}

// ===========================================================================
extern "C" void kernel_launch(void* const* d_in, const int* in_sizes, int n_in,
                              void* d_out, int out_size)
{
    const float* x    = (const float*)d_in[0];
    const float* mask = (const float*)d_in[1];
    const float* img  = (const float*)d_in[2];
    const float* Wfc  = (const float*)d_in[3];
    const float* bfc  = (const float*)d_in[4];
    const float* Wl   = (const float*)d_in[5];
    const float* bl   = (const float*)d_in[6];
    const float* Wm   = (const float*)d_in[7];
    const float* bm   = (const float*)d_in[8];
    const float* Ws   = (const float*)d_in[9];
    const float* bsv  = (const float*)d_in[10];

    float* out_ff  = (float*)d_out;                 // [16,64,768]
    float* out_img = (float*)d_out + FF_ELEMS;      // [16,3,224,224]

    conv_w_kernel<<<(992 * 768 + 255) / 256, 256>>>(Wfc, Wl, Wm, Ws, bl, bm, bsv);

    cudaFuncSetAttribute(fc_mma_kernel,
                         cudaFuncAttributeMaxDynamicSharedMemorySize, FC_SMEM);
    fc_mma_kernel<<<M_ROWS / 64, 256, FC_SMEM>>>(x, bfc);

    sel_kernel<<<BATCH, 128>>>(mask);
    {
        dim3 g(64, BATCH, 3);
        gather_kernel<<<g, 256>>>(x);
    }
    {
        dim3 g(16, 12);
        parts_mma_kernel<<<g, 256>>>(out_ff);
    }
    image_kernel<<<(IMG_OUT_ELEMS + 255) / 256, 256>>>(img, out_img);
}

// round 7
// speedup vs baseline: 3.2521x; 1.1086x over previous
#include <cuda_runtime.h>
#include <cuda_bf16.h>
#include <math.h>

typedef unsigned int uint;

#define C_DIM   768
#define NCLS    200
#define BATCH   16
#define M_ROWS  (BATCH * 784)   // 12544
#define NPAD    224
#define FF_ELEMS (BATCH * 64 * 768)              // 786432
#define IMG_OUT_ELEMS (BATCH * 3 * 224 * 224)    // 2408448

// ---------------- scratch (device globals; no runtime alloc allowed) -------
__device__ float g_maxprob[M_ROWS];
__device__ int   g_sel[BATCH];
__device__ __align__(16) __nv_bfloat16 g_Wfch[NPAD * C_DIM];
__device__ __align__(16) __nv_bfloat16 g_Wfcl[NPAD * C_DIM];
__device__ __align__(16) __nv_bfloat16 g_Wph[768 * C_DIM];
__device__ __align__(16) __nv_bfloat16 g_Wpl[768 * C_DIM];
__device__ __align__(16) float g_bias[768];
__device__ __align__(16) __nv_bfloat16 g_Ah[3][1024 * C_DIM];
__device__ __align__(16) __nv_bfloat16 g_Al[3][1024 * C_DIM];

__device__ __forceinline__ uint b2u(__nv_bfloat162 v) {
    return *reinterpret_cast<uint*>(&v);
}
__device__ __forceinline__ uint smem_u32(const void* p) {
    return (uint)__cvta_generic_to_shared(p);
}
// float4 -> bf16 hi uint2 + lo uint2
__device__ __forceinline__ void split4(float4 v, uint2& hv, uint2& lv) {
    __nv_bfloat162 h01 = __floats2bfloat162_rn(v.x, v.y);
    __nv_bfloat162 h23 = __floats2bfloat162_rn(v.z, v.w);
    float2 f01 = __bfloat1622float2(h01), f23 = __bfloat1622float2(h23);
    hv = make_uint2(b2u(h01), b2u(h23));
    lv = make_uint2(b2u(__floats2bfloat162_rn(v.x - f01.x, v.y - f01.y)),
                    b2u(__floats2bfloat162_rn(v.z - f23.x, v.w - f23.y)));
}

#define MMA_BF16(c0,c1,c2,c3,a0,a1,a2,a3,b0,b1)                              \
    asm volatile("mma.sync.aligned.m16n8k16.row.col.f32.bf16.bf16.f32 "      \
        "{%0,%1,%2,%3}, {%4,%5,%6,%7}, {%8,%9}, {%0,%1,%2,%3};"              \
        : "+f"(c0), "+f"(c1), "+f"(c2), "+f"(c3)                             \
        : "r"(a0), "r"(a1), "r"(a2), "r"(a3), "r"(b0), "r"(b1))

#define LDSM_X4(r0,r1,r2,r3,addr)                                            \
    asm volatile("ldmatrix.sync.aligned.m8n8.x4.shared.b16 {%0,%1,%2,%3}, [%4];" \
        : "=r"(r0), "=r"(r1), "=r"(r2), "=r"(r3) : "r"(addr))

#define CP_ASYNC16(dst, src) \
    asm volatile("cp.async.cg.shared.global [%0], [%1], 16;" :: "r"(dst), "l"(src))
#define CP_COMMIT() asm volatile("cp.async.commit_group;")
#define CP_WAIT0()  asm volatile("cp.async.wait_group 0;")

// ===========================================================================
// Kernel 0: weight conversion (vectorized x4) + bias concat.
// ===========================================================================
#define FC4 (NPAD * C_DIM / 4)    // 43008
#define P4  (768 * C_DIM / 4)     // 147456

__global__ void conv_w_kernel(const float* __restrict__ Wfc,
                              const float* __restrict__ Wl,
                              const float* __restrict__ Wm,
                              const float* __restrict__ Ws,
                              const float* __restrict__ bl,
                              const float* __restrict__ bm,
                              const float* __restrict__ bsv)
{
    int idx = blockIdx.x * blockDim.x + threadIdx.x;
    if (idx < FC4) {
        int row = idx / 192, kq = idx % 192;
        float4 v = (row < NCLS) ? *(const float4*)&Wfc[(size_t)row * C_DIM + kq * 4]
                                : make_float4(0.f, 0.f, 0.f, 0.f);
        uint2 hv, lv; split4(v, hv, lv);
        *(uint2*)&g_Wfch[idx * 4] = hv;
        *(uint2*)&g_Wfcl[idx * 4] = lv;
    } else if (idx < FC4 + P4) {
        int j = idx - FC4;
        int row = j / 192, kq = j % 192;
        const float* src = (row < 192) ? &Wl[(size_t)row * C_DIM]
                         : (row < 384) ? &Wm[(size_t)(row - 192) * C_DIM]
                                       : &Ws[(size_t)(row - 384) * C_DIM];
        float4 v = *(const float4*)&src[kq * 4];
        uint2 hv, lv; split4(v, hv, lv);
        *(uint2*)&g_Wph[j * 4] = hv;
        *(uint2*)&g_Wpl[j * 4] = lv;
    }
    if (idx < 768)
        g_bias[idx] = (idx < 192) ? bl[idx]
                    : (idx < 384) ? bm[idx - 192] : bsv[idx - 384];
}

// ===========================================================================
// Kernel 1: fc GEMM (HMMA bf16 3-chain split) + fused softmax-max reduce.
// CTA: 64 rows x 224 cols. 256 thr = 8 warps. BK=32, 24 steps, double-buf,
// ldmatrix frags, cp.async W tiles. Row stride 40 bf16 (conflict-free).
// ===========================================================================
#define FC_ST      40                      // bf16 row stride
#define FC_XBUF_B  (64 * FC_ST * 2)        // 5120 B per X buffer per precision
#define FC_WBUF_B  (224 * FC_ST * 2)       // 17920 B
#define FC_SMEM    (4 * FC_XBUF_B + 4 * FC_WBUF_B + 1024)   // 93184

__global__ __launch_bounds__(256, 2)
void fc_mma_kernel(const float* __restrict__ x, const float* __restrict__ bfc)
{
    extern __shared__ __align__(16) char sm_raw[];
    __nv_bfloat16* sxh = (__nv_bfloat16*)sm_raw;
    __nv_bfloat16* sxl = (__nv_bfloat16*)(sm_raw + 2 * FC_XBUF_B);
    __nv_bfloat16* swh = (__nv_bfloat16*)(sm_raw + 4 * FC_XBUF_B);
    __nv_bfloat16* swl = (__nv_bfloat16*)(sm_raw + 4 * FC_XBUF_B + 2 * FC_WBUF_B);
    float* red = (float*)(sm_raw + 4 * FC_XBUF_B + 4 * FC_WBUF_B);  // [2][2][64]

    const int tid = threadIdx.x, lane = tid & 31, warp = tid >> 5;
    const int g = lane >> 2, t = lane & 3;
    const int wm = warp & 3, wn = warp >> 2;
    const int m0 = blockIdx.x * 64;

    // ---- X fill: row = tid>>2, kq = tid&3; two float4 per step (k and k+16)
    const int xrow = tid >> 2, xkq = tid & 3;
    const float4* xp = (const float4*)(x + (size_t)(m0 + xrow) * C_DIM);
    char* sxh_dst = (char*)(sxh + xrow * FC_ST + xkq * 4);
    char* sxl_dst = (char*)(sxl + xrow * FC_ST + xkq * 4);

    // ---- W fill: 1792 16B chunks/step = 7 per thread (exact)
    const __nv_bfloat16* wsrc[7];
    uint wdst[7];
#pragma unroll
    for (int it = 0; it < 7; it++) {
        int idx = tid + it * 256;
        int prec = idx >= 896;
        int rr = prec ? idx - 896 : idx;
        int row = rr >> 2, q = rr & 3;
        wsrc[it] = (prec ? g_Wfcl : g_Wfch) + (size_t)row * C_DIM + q * 8;
        wdst[it] = smem_u32((prec ? swl : swh) + row * FC_ST + q * 8);
    }

    // ---- ldmatrix lane base addresses (buffer 0, chunk 0)
    const uint a_base  = (uint)((wm * 16 + (lane & 15)) * FC_ST + (lane >> 4) * 8) * 2;
    const uint ah_addr = smem_u32(sxh) + a_base;
    const uint al_addr = smem_u32(sxl) + a_base;
    const uint b_base  = (uint)((wn * 112 + ((lane >> 4) & 1) * 8 + (lane & 7)) * FC_ST
                                + ((lane >> 3) & 1) * 8) * 2;
    const uint bh_addr = smem_u32(swh) + b_base;
    const uint bl_addr = smem_u32(swl) + b_base;

    float acc[14][4];
#pragma unroll
    for (int j = 0; j < 14; j++)
#pragma unroll
        for (int q = 0; q < 4; q++) acc[j][q] = 0.f;

    // ---- prologue: tile 0
    float4 xr0 = xp[xkq], xr1 = xp[4 + xkq];
#pragma unroll
    for (int it = 0; it < 7; it++) CP_ASYNC16(wdst[it], wsrc[it]);
    CP_COMMIT();
    {
        uint2 hv, lv;
        split4(xr0, hv, lv);
        *(uint2*)sxh_dst = hv; *(uint2*)sxl_dst = lv;
        split4(xr1, hv, lv);
        *(uint2*)(sxh_dst + 32) = hv; *(uint2*)(sxl_dst + 32) = lv;
    }
    CP_WAIT0();
    __syncthreads();

    for (int step = 0; step < 24; step++) {
        const int buf = step & 1;
        const uint xoff  = (uint)buf * FC_XBUF_B;
        const uint woff  = (uint)buf * FC_WBUF_B;
        const uint nxoff = (uint)(buf ^ 1) * FC_XBUF_B;
        const uint nwoff = (uint)(buf ^ 1) * FC_WBUF_B;

        if (step < 23) {
            xr0 = xp[(step + 1) * 8 + xkq];
            xr1 = xp[(step + 1) * 8 + 4 + xkq];
#pragma unroll
            for (int it = 0; it < 7; it++)
                CP_ASYNC16(wdst[it] + nwoff, wsrc[it] + (step + 1) * 32);
            CP_COMMIT();
        }

#pragma unroll
        for (int c = 0; c < 2; c++) {
            const uint coff = c * 32;       // +16 bf16 columns
            uint ah[4], al[4];
            LDSM_X4(ah[0], ah[1], ah[2], ah[3], ah_addr + xoff + coff);
            LDSM_X4(al[0], al[1], al[2], al[3], al_addr + xoff + coff);
#pragma unroll
            for (int jp = 0; jp < 7; jp++) {
                uint bh[4], bl[4];
                LDSM_X4(bh[0], bh[1], bh[2], bh[3], bh_addr + woff + jp * 1280 + coff);
                LDSM_X4(bl[0], bl[1], bl[2], bl[3], bl_addr + woff + jp * 1280 + coff);
                const int j0 = 2 * jp, j1 = j0 + 1;
                MMA_BF16(acc[j0][0], acc[j0][1], acc[j0][2], acc[j0][3],
                         ah[0], ah[1], ah[2], ah[3], bh[0], bh[1]);
                MMA_BF16(acc[j0][0], acc[j0][1], acc[j0][2], acc[j0][3],
                         ah[0], ah[1], ah[2], ah[3], bl[0], bl[1]);
                MMA_BF16(acc[j0][0], acc[j0][1], acc[j0][2], acc[j0][3],
                         al[0], al[1], al[2], al[3], bh[0], bh[1]);
                MMA_BF16(acc[j1][0], acc[j1][1], acc[j1][2], acc[j1][3],
                         ah[0], ah[1], ah[2], ah[3], bh[2], bh[3]);
                MMA_BF16(acc[j1][0], acc[j1][1], acc[j1][2], acc[j1][3],
                         ah[0], ah[1], ah[2], ah[3], bl[2], bl[3]);
                MMA_BF16(acc[j1][0], acc[j1][1], acc[j1][2], acc[j1][3],
                         al[0], al[1], al[2], al[3], bh[2], bh[3]);
            }
        }

        if (step < 23) {
            uint2 hv, lv;
            split4(xr0, hv, lv);
            *(uint2*)(sxh_dst + nxoff) = hv; *(uint2*)(sxl_dst + nxoff) = lv;
            split4(xr1, hv, lv);
            *(uint2*)(sxh_dst + nxoff + 32) = hv; *(uint2*)(sxl_dst + nxoff + 32) = lv;
            CP_WAIT0();
        }
        __syncthreads();
    }

    // ---- epilogue: bias + mask, fused row max / sumexp reduce ----
#pragma unroll
    for (int j = 0; j < 14; j++) {
        int col = wn * 112 + j * 8 + t * 2;
        if (col < NCLS) { float b = bfc[col]; acc[j][0] += b; acc[j][2] += b; }
        else            { acc[j][0] = acc[j][2] = -1e30f; }
        if (col + 1 < NCLS) { float b = bfc[col + 1]; acc[j][1] += b; acc[j][3] += b; }
        else                { acc[j][1] = acc[j][3] = -1e30f; }
    }
    const int r0 = wm * 16 + g, r1 = r0 + 8;
    float mx0 = -1e30f, mx1 = -1e30f;
#pragma unroll
    for (int j = 0; j < 14; j++) {
        mx0 = fmaxf(mx0, fmaxf(acc[j][0], acc[j][1]));
        mx1 = fmaxf(mx1, fmaxf(acc[j][2], acc[j][3]));
    }
#pragma unroll
    for (int off = 1; off <= 2; off <<= 1) {
        mx0 = fmaxf(mx0, __shfl_xor_sync(0xffffffffu, mx0, off));
        mx1 = fmaxf(mx1, __shfl_xor_sync(0xffffffffu, mx1, off));
    }
    if (t == 0) { red[wn * 64 + r0] = mx0; red[wn * 64 + r1] = mx1; }
    __syncthreads();
    const float rm0 = fmaxf(red[r0], red[64 + r0]);
    const float rm1 = fmaxf(red[r1], red[64 + r1]);
    float s0 = 0.f, s1 = 0.f;
#pragma unroll
    for (int j = 0; j < 14; j++) {
        s0 += expf(acc[j][0] - rm0) + expf(acc[j][1] - rm0);
        s1 += expf(acc[j][2] - rm1) + expf(acc[j][3] - rm1);
    }
#pragma unroll
    for (int off = 1; off <= 2; off <<= 1) {
        s0 += __shfl_xor_sync(0xffffffffu, s0, off);
        s1 += __shfl_xor_sync(0xffffffffu, s1, off);
    }
    if (t == 0) { red[128 + wn * 64 + r0] = s0; red[128 + wn * 64 + r1] = s1; }
    __syncthreads();
    if (wn == 0 && t == 0) {
        g_maxprob[m0 + r0] = 1.f / (red[128 + r0] + red[128 + 64 + r0]);
        g_maxprob[m0 + r1] = 1.f / (red[128 + r1] + red[128 + 64 + r1]);
    }
}

// ===========================================================================
// Kernel 2: part_logits (8x8 mean-pool, stride 3, pad 2) * mask -> argmax
// ===========================================================================
__global__ void sel_kernel(const float* __restrict__ mask)
{
    int b = blockIdx.x;
    __shared__ float map[784];
    __shared__ float vals[81];
    int p = threadIdx.x;
    for (int i = p; i < 784; i += 128) map[i] = g_maxprob[b * 784 + i];
    __syncthreads();
    if (p < 81) {
        int oy = p / 9, ox = p % 9;
        float s = 0.f;
#pragma unroll
        for (int i = 0; i < 8; i++) {
            int h = oy * 3 - 2 + i;
            if (h < 0 || h >= 28) continue;
#pragma unroll
            for (int j = 0; j < 8; j++) {
                int w = ox * 3 - 2 + j;
                if (w < 0 || w >= 28) continue;
                s += map[h * 28 + w];
            }
        }
        vals[p] = mask[b * 81 + p] * (s * (1.f / 64.f));
    }
    __syncthreads();
    if (p == 0) {
        float best = vals[0];
        int bi = 0;
        for (int q = 1; q < 81; q++)
            if (vals[q] > best) { best = vals[q]; bi = q; }
        g_sel[b] = bi;
    }
}

// ===========================================================================
// Kernel 3: gather selected patches -> bf16 hi/lo A matrices (x4 vectorized)
// grid (64, 16, 3), 192 threads: thread handles 4 channels.
// ===========================================================================
__global__ void gather_kernel(const float* __restrict__ x)
{
    int p    = blockIdx.x;
    int b    = blockIdx.y;
    int part = blockIdx.z;
    int sel  = g_sel[b];
    int oy = sel / 9, ox = sel % 9;
    int i = p >> 3, j = p & 7;
    int c = threadIdx.x * 4;

    const float* xb = x + (size_t)b * 784 * C_DIM;
    __nv_bfloat16* oh = &g_Ah[part][(size_t)(b * 64 + p) * C_DIM + c];
    __nv_bfloat16* ol = &g_Al[part][(size_t)(b * 64 + p) * C_DIM + c];

    float4 v;
    if (part == 0) {
        int h = oy * 3 - 2 + i, w = ox * 3 - 2 + j;
        bool ok = (h >= 0 && h < 28 && w >= 0 && w < 28);
        v = ok ? *(const float4*)&xb[(size_t)(h * 28 + w) * C_DIM + c]
               : make_float4(0.f, 0.f, 0.f, 0.f);
    } else {
        int   n, basepad;
        float scale, offs;
        if (part == 1) { n = 6; basepad = 1; scale = 0.75f; offs = -0.125f; }
        else           { n = 4; basepad = 0; scale = 0.5f;  offs = -0.25f;  }
        float sy = fminf(fmaxf(scale * i + offs, 0.f), (float)(n - 1));
        float sx = fminf(fmaxf(scale * j + offs, 0.f), (float)(n - 1));
        int iy0 = (int)sy; float fy = sy - iy0; int iy1 = min(iy0 + 1, n - 1);
        int ix0 = (int)sx; float fx = sx - ix0; int ix1 = min(ix0 + 1, n - 1);
        int hb = oy * 3 - basepad, wb = ox * 3 - basepad;
        int h0 = hb + iy0, h1 = hb + iy1, w0 = wb + ix0, w1 = wb + ix1;
        bool okh0 = (h0 >= 0 && h0 < 28), okh1 = (h1 >= 0 && h1 < 28);
        bool okw0 = (w0 >= 0 && w0 < 28), okw1 = (w1 >= 0 && w1 < 28);
        bool ok00 = okh0 && okw0, ok01 = okh0 && okw1;
        bool ok10 = okh1 && okw0, ok11 = okh1 && okw1;
        const float4 z = make_float4(0.f, 0.f, 0.f, 0.f);
        float4 v00 = ok00 ? *(const float4*)&xb[(size_t)(h0 * 28 + w0) * C_DIM + c] : z;
        float4 v01 = ok01 ? *(const float4*)&xb[(size_t)(h0 * 28 + w1) * C_DIM + c] : z;
        float4 v10 = ok10 ? *(const float4*)&xb[(size_t)(h1 * 28 + w0) * C_DIM + c] : z;
        float4 v11 = ok11 ? *(const float4*)&xb[(size_t)(h1 * 28 + w1) * C_DIM + c] : z;
        float gy = 1.f - fy, gx = 1.f - fx;
        v.x = gy * (gx * v00.x + fx * v01.x) + fy * (gx * v10.x + fx * v11.x);
        v.y = gy * (gx * v00.y + fx * v01.y) + fy * (gx * v10.y + fx * v11.y);
        v.z = gy * (gx * v00.z + fx * v01.z) + fy * (gx * v10.z + fx * v11.z);
        v.w = gy * (gx * v00.w + fx * v01.w) + fy * (gx * v10.w + fx * v11.w);
    }
    uint2 hv, lv; split4(v, hv, lv);
    *(uint2*)oh = hv;
    *(uint2*)ol = lv;
}

// ===========================================================================
// Kernel 4: parts GEMM (HMMA 3-chain).  BM=64, BN=64, grid(16,12), 256 thr.
// ===========================================================================
#define P_BUF (64 * 24)

__global__ __launch_bounds__(256, 3)
void parts_mma_kernel(float* __restrict__ out)
{
    __shared__ __align__(16) __nv_bfloat16 sah[2][P_BUF], sal[2][P_BUF];
    __shared__ __align__(16) __nv_bfloat16 swh[2][P_BUF], swl[2][P_BUF];

    const int tid = threadIdx.x, lane = tid & 31, warp = tid >> 5;
    const int g = lane >> 2, t = lane & 3;
    const int wm = warp & 3, wn = warp >> 2;
    const int m0 = blockIdx.x * 64;
    const int n0c = blockIdx.y * 64;
    const int part = (n0c < 192) ? 0 : (n0c < 384) ? 1 : 2;

    const int prec = tid >= 128, rr = tid & 127;
    const int frow = rr >> 1, fhalf = rr & 1;
    const __nv_bfloat16* asrc =
        (prec ? g_Al[part] : g_Ah[part]) + (size_t)(m0 + frow) * C_DIM + fhalf * 8;
    const __nv_bfloat16* wsrc =
        (prec ? g_Wpl : g_Wph) + (size_t)(n0c + frow) * C_DIM + fhalf * 8;
    const uint adst = smem_u32((prec ? sal[0] : sah[0]) + frow * 24 + fhalf * 8);
    const uint wdst = smem_u32((prec ? swl[0] : swh[0]) + frow * 24 + fhalf * 8);

    const uint a_base  = (uint)((wm * 16 + (lane & 15)) * 24 + (lane >> 4) * 8) * 2;
    const uint ah_addr = smem_u32(sah[0]) + a_base;
    const uint al_addr = smem_u32(sal[0]) + a_base;
    const uint b_base  = (uint)((wn * 32 + ((lane >> 4) & 1) * 8 + (lane & 7)) * 24
                                + ((lane >> 3) & 1) * 8) * 2;
    const uint bh_addr = smem_u32(swh[0]) + b_base;
    const uint bl_addr = smem_u32(swl[0]) + b_base;

    float acc[4][4];
#pragma unroll
    for (int j = 0; j < 4; j++)
#pragma unroll
        for (int q = 0; q < 4; q++) acc[j][q] = 0.f;

    CP_ASYNC16(adst, asrc);
    CP_ASYNC16(wdst, wsrc);
    CP_COMMIT();
    CP_WAIT0();
    __syncthreads();

    for (int step = 0; step < 48; step++) {
        const int buf = step & 1;
        const uint off  = (uint)buf * (P_BUF * 2);
        const uint noff = (uint)(buf ^ 1) * (P_BUF * 2);

        if (step < 47) {
            CP_ASYNC16(adst + noff, asrc + (step + 1) * 16);
            CP_ASYNC16(wdst + noff, wsrc + (step + 1) * 16);
            CP_COMMIT();
        }

        uint ah[4], al[4];
        LDSM_X4(ah[0], ah[1], ah[2], ah[3], ah_addr + off);
        LDSM_X4(al[0], al[1], al[2], al[3], al_addr + off);
#pragma unroll
        for (int jp = 0; jp < 2; jp++) {
            uint bh[4], bl[4];
            LDSM_X4(bh[0], bh[1], bh[2], bh[3], bh_addr + off + jp * 768);
            LDSM_X4(bl[0], bl[1], bl[2], bl[3], bl_addr + off + jp * 768);
            const int j0 = 2 * jp, j1 = j0 + 1;
            MMA_BF16(acc[j0][0], acc[j0][1], acc[j0][2], acc[j0][3],
                     ah[0], ah[1], ah[2], ah[3], bh[0], bh[1]);
            MMA_BF16(acc[j0][0], acc[j0][1], acc[j0][2], acc[j0][3],
                     ah[0], ah[1], ah[2], ah[3], bl[0], bl[1]);
            MMA_BF16(acc[j0][0], acc[j0][1], acc[j0][2], acc[j0][3],
                     al[0], al[1], al[2], al[3], bh[0], bh[1]);
            MMA_BF16(acc[j1][0], acc[j1][1], acc[j1][2], acc[j1][3],
                     ah[0], ah[1], ah[2], ah[3], bh[2], bh[3]);
            MMA_BF16(acc[j1][0], acc[j1][1], acc[j1][2], acc[j1][3],
                     ah[0], ah[1], ah[2], ah[3], bl[2], bl[3]);
            MMA_BF16(acc[j1][0], acc[j1][1], acc[j1][2], acc[j1][3],
                     al[0], al[1], al[2], al[3], bh[2], bh[3]);
        }

        if (step < 47) CP_WAIT0();
        __syncthreads();
    }

#pragma unroll
    for (int j = 0; j < 4; j++) {
        int col = n0c + wn * 32 + j * 8 + t * 2;
        int m   = m0 + wm * 16 + g;
        float2 bc = *(float2*)&g_bias[col];
        *(float2*)&out[(size_t)m * 768 + col] =
            make_float2(acc[j][0] + bc.x, acc[j][1] + bc.y);
        *(float2*)&out[(size_t)(m + 8) * 768 + col] =
            make_float2(acc[j][2] + bc.x, acc[j][3] + bc.y);
    }
}

// ===========================================================================
// Kernel 5: image patch gather + bilinear 224.  grid (48, 224), 224 thr.
// ===========================================================================
__global__ void image_kernel(const float* __restrict__ img, float* __restrict__ out)
{
    int bc = blockIdx.x;            // b*3 + ch
    int b  = bc / 3;
    int oy = blockIdx.y;
    int ox = threadIdx.x;

    int sel = g_sel[b];
    int r0 = (sel / 9) * 48 - 32;
    int c0 = (sel % 9) * 48 - 32;

    const float s = 128.f / 224.f;
    float sy = fminf(fmaxf((oy + 0.5f) * s - 0.5f, 0.f), 127.f);
    float sx = fminf(fmaxf((ox + 0.5f) * s - 0.5f, 0.f), 127.f);
    int py0 = (int)sy; float fy = sy - py0; int py1 = min(py0 + 1, 127);
    int px0 = (int)sx; float fx = sx - px0; int px1 = min(px0 + 1, 127);

    const float* ib = img + (size_t)bc * 448 * 448;
    int gy0 = r0 + py0, gy1 = r0 + py1, gx0 = c0 + px0, gx1 = c0 + px1;
    bool oky0 = (gy0 >= 0 && gy0 < 448), oky1 = (gy1 >= 0 && gy1 < 448);
    bool okx0 = (gx0 >= 0 && gx0 < 448), okx1 = (gx1 >= 0 && gx1 < 448);
    float v00 = (oky0 && okx0) ? ib[gy0 * 448 + gx0] : 0.f;
    float v01 = (oky0 && okx1) ? ib[gy0 * 448 + gx1] : 0.f;
    float v10 = (oky1 && okx0) ? ib[gy1 * 448 + gx0] : 0.f;
    float v11 = (oky1 && okx1) ? ib[gy1 * 448 + gx1] : 0.f;

    out[((size_t)bc * 224 + oy) * 224 + ox] =
        (1.f - fy) * ((1.f - fx) * v00 + fx * v01)
      +        fy  * ((1.f - fx) * v10 + fx * v11);
}

// ===========================================================================
extern "C" void kernel_launch(void* const* d_in, const int* in_sizes, int n_in,
                              void* d_out, int out_size)
{
    const float* x    = (const float*)d_in[0];
    const float* mask = (const float*)d_in[1];
    const float* img  = (const float*)d_in[2];
    const float* Wfc  = (const float*)d_in[3];
    const float* bfc  = (const float*)d_in[4];
    const float* Wl   = (const float*)d_in[5];
    const float* bl   = (const float*)d_in[6];
    const float* Wm   = (const float*)d_in[7];
    const float* bm   = (const float*)d_in[8];
    const float* Ws   = (const float*)d_in[9];
    const float* bsv  = (const float*)d_in[10];

    float* out_ff  = (float*)d_out;                 // [16,64,768]
    float* out_img = (float*)d_out + FF_ELEMS;      // [16,3,224,224]

    conv_w_kernel<<<(FC4 + P4 + 255) / 256, 256>>>(Wfc, Wl, Wm, Ws, bl, bm, bsv);

    cudaFuncSetAttribute(fc_mma_kernel,
                         cudaFuncAttributeMaxDynamicSharedMemorySize, FC_SMEM);
    fc_mma_kernel<<<M_ROWS / 64, 256, FC_SMEM>>>(x, bfc);

    sel_kernel<<<BATCH, 128>>>(mask);
    {
        dim3 g(64, BATCH, 3);
        gather_kernel<<<g, 192>>>(x);
    }
    {
        dim3 g(16, 12);
        parts_mma_kernel<<<g, 256>>>(out_ff);
    }
    {
        dim3 g(48, 224);
        image_kernel<<<g, 224>>>(img, out_img);
    }
}